// round 13
// baseline (speedup 1.0000x reference)
#include <cuda_runtime.h>
#include <cuda_bf16.h>
#include <math.h>
#include <stdint.h>

#define LL    1024
#define BSZ   8
#define DQK   256
#define DEXP  512
#define NHEAD 8
#define HDIM  64
#define DATT  32
#define MROWS (LL*BSZ)   // 8192
#define HALF_OUT 256
#define SPITCH 1032
#define KPITCH 40
#define QPITCH 40
#define VPITCH 68
#define RPITCH 72
#define AROWS  32

// ---------------- scratch ----------------
__device__ __align__(256) uint32_t g_Qps[MROWS*DQK];   // packed Qp (post-GEMM)
__device__ __align__(256) uint32_t g_Vps[MROWS*DEXP];  // packed Vc
__device__ __align__(256) float    g_Uc [MROWS*DEXP];
__device__ __align__(256) float    g_G  [MROWS*DEXP];
__device__ __align__(256) uint32_t g_Yp [MROWS*DEXP];  // packed conv output
// packed inputs/weights
__device__ __align__(256) uint32_t g_Qin[MROWS*DQK];
__device__ __align__(256) uint32_t g_Vin[MROWS*DQK];
__device__ __align__(256) uint32_t g_Uin[MROWS*DQK];
__device__ __align__(256) uint32_t g_Wqk[DQK*DQK];
__device__ __align__(256) uint32_t g_Wv1[128*HALF_OUT];
__device__ __align__(256) uint32_t g_Wv2[128*HALF_OUT];
__device__ __align__(256) uint32_t g_Wu1[128*HALF_OUT];
__device__ __align__(256) uint32_t g_Wu2[128*HALF_OUT];
__device__ __align__(256) uint32_t g_Wpp[DEXP*DQK];

// ---------------- helpers ----------------
__device__ __forceinline__ uint32_t bf16_split_elem(float x) {
    __nv_bfloat16 hb = __float2bfloat16_rn(x);
    float hf = __bfloat162float(hb);
    __nv_bfloat16 lb = __float2bfloat16_rn(x - hf);
    return ((uint32_t)__bfloat16_as_ushort(lb) << 16) | (uint32_t)__bfloat16_as_ushort(hb);
}
__device__ __forceinline__ float bf16_unsplit(uint32_t p) {
    return __uint_as_float(p << 16) + __uint_as_float(p & 0xffff0000u);
}

__device__ __forceinline__ void mma_bf16(float* c, const uint32_t* a, const uint32_t* b) {
    asm volatile(
        "mma.sync.aligned.m16n8k16.row.col.f32.bf16.bf16.f32 "
        "{%0,%1,%2,%3},{%4,%5,%6,%7},{%8,%9},{%0,%1,%2,%3};"
        : "+f"(c[0]), "+f"(c[1]), "+f"(c[2]), "+f"(c[3])
        : "r"(a[0]), "r"(a[1]), "r"(a[2]), "r"(a[3]), "r"(b[0]), "r"(b[1]));
}

#define PERM_HI(p0, p1) __byte_perm((p0), (p1), 0x5410)
#define PERM_LO(p0, p1) __byte_perm((p0), (p1), 0x7632)

// ---------------- pack: fp32 -> packed bf16(hi,lo) ----------------
__global__ __launch_bounds__(256) void pack_kernel(
    const float* __restrict__ src, uint32_t* __restrict__ dst, int n)
{
    int i = blockIdx.x * 256 + threadIdx.x;
    if (i < n) dst[i] = bf16_split_elem(src[i]);
}

// ---------------- tensor-core GEMM + bias, PACKED operands ----------------
__global__ __launch_bounds__(256) void mma_gemm_kernel(
    const uint32_t* __restrict__ A, const uint32_t* __restrict__ B,
    const float* __restrict__ bias, void* __restrict__ Cv,
    int M, int N, int K, int mode)
{
    __shared__ uint32_t As[64*40];
    __shared__ uint32_t Bs[32*68];
    const int m0 = blockIdx.y * 64, n0 = blockIdx.x * 64;
    const int tid = threadIdx.x, lane = tid & 31, w = tid >> 5;
    const int g = lane >> 2, t = lane & 3;
    const int mw = w >> 2, nq = w & 3;

    uint32_t aReg[8], bReg[8];
    #pragma unroll
    for (int i = 0; i < 8; i++) {
        int idx = 256*i + tid;
        aReg[i] = A[(size_t)(m0 + (idx >> 5)) * K + (idx & 31)];
        bReg[i] = B[(size_t)(idx >> 6) * N + n0 + (idx & 63)];
    }
    float acc[2][2][4] = {};

    for (int k0 = 0; k0 < K; k0 += 32) {
        #pragma unroll
        for (int i = 0; i < 8; i++) {
            int idx = 256*i + tid;
            As[(idx >> 5)*40 + (idx & 31)] = aReg[i];
            Bs[(idx >> 6)*68 + (idx & 63)] = bReg[i];
        }
        __syncthreads();
        if (k0 + 32 < K) {
            #pragma unroll
            for (int i = 0; i < 8; i++) {
                int idx = 256*i + tid;
                aReg[i] = A[(size_t)(m0 + (idx >> 5)) * K + k0 + 32 + (idx & 31)];
                bReg[i] = B[(size_t)(k0 + 32 + (idx >> 6)) * N + n0 + (idx & 63)];
            }
        }
        #pragma unroll
        for (int ks = 0; ks < 2; ks++) {
            uint32_t ah[2][4], al[2][4];
            #pragma unroll
            for (int mt = 0; mt < 2; mt++) {
                int r = mw*32 + mt*16 + g;
                int d = ks*16 + 2*t;
                uint2 p0 = *(const uint2*)&As[r*40 + d];
                uint2 p1 = *(const uint2*)&As[(r+8)*40 + d];
                uint2 p2 = *(const uint2*)&As[r*40 + d + 8];
                uint2 p3 = *(const uint2*)&As[(r+8)*40 + d + 8];
                ah[mt][0] = PERM_HI(p0.x, p0.y); al[mt][0] = PERM_LO(p0.x, p0.y);
                ah[mt][1] = PERM_HI(p1.x, p1.y); al[mt][1] = PERM_LO(p1.x, p1.y);
                ah[mt][2] = PERM_HI(p2.x, p2.y); al[mt][2] = PERM_LO(p2.x, p2.y);
                ah[mt][3] = PERM_HI(p3.x, p3.y); al[mt][3] = PERM_LO(p3.x, p3.y);
            }
            #pragma unroll
            for (int nt = 0; nt < 2; nt++) {
                int nn = nq*16 + nt*8 + g;
                int kk = ks*16 + 2*t;
                uint32_t q0 = Bs[kk*68 + nn];
                uint32_t q1 = Bs[(kk+1)*68 + nn];
                uint32_t q2 = Bs[(kk+8)*68 + nn];
                uint32_t q3 = Bs[(kk+9)*68 + nn];
                uint32_t bfh[2] = {PERM_HI(q0, q1), PERM_HI(q2, q3)};
                uint32_t bfl[2] = {PERM_LO(q0, q1), PERM_LO(q2, q3)};
                #pragma unroll
                for (int mt = 0; mt < 2; mt++) {
                    mma_bf16(acc[mt][nt], ah[mt], bfh);
                    mma_bf16(acc[mt][nt], ah[mt], bfl);
                    mma_bf16(acc[mt][nt], al[mt], bfh);
                }
            }
        }
        __syncthreads();
    }

    #pragma unroll
    for (int mt = 0; mt < 2; mt++) {
        int row = m0 + mw*32 + mt*16 + g;
        #pragma unroll
        for (int nt = 0; nt < 2; nt++) {
            int col = n0 + nq*16 + nt*8 + 2*t;
            float b0 = bias[col], b1 = bias[col+1];
            float v0 = acc[mt][nt][0] + b0, v1 = acc[mt][nt][1] + b1;
            float v2 = acc[mt][nt][2] + b0, v3 = acc[mt][nt][3] + b1;
            if (mode == 0) {
                float* C = (float*)Cv;
                C[(size_t)row*N + col]       = v0;
                C[(size_t)row*N + col + 1]   = v1;
                C[(size_t)(row+8)*N + col]     = v2;
                C[(size_t)(row+8)*N + col + 1] = v3;
            } else {
                uint32_t* C = (uint32_t*)Cv;
                C[(size_t)row*N + col]       = bf16_split_elem(v0);
                C[(size_t)row*N + col + 1]   = bf16_split_elem(v1);
                C[(size_t)(row+8)*N + col]     = bf16_split_elem(v2);
                C[(size_t)(row+8)*N + col + 1] = bf16_split_elem(v3);
            }
        }
    }
}

// ---------------- tensor-core gated half-projection + SiLU, PACKED operands ----------------
__global__ __launch_bounds__(256) void mma_gated_kernel(
    const uint32_t* __restrict__ X,
    const uint32_t* __restrict__ W1, const float* __restrict__ b1,
    const uint32_t* __restrict__ W2, const float* __restrict__ b2,
    void* __restrict__ Yv, int packed)
{
    __shared__ uint32_t As[64*40];
    __shared__ uint32_t Bs[32*36];
    const int c0   = blockIdx.x * 32;
    const int head = c0 >> 6;
    const int is2  = (c0 >> 5) & 1;
    const uint32_t* W  = is2 ? W2 : W1;
    const float* bb = is2 ? b2 : b1;
    const int wc0 = head * 32;
    const uint32_t* Ain = X + (is2 ? 128 : 0);
    const int m0 = blockIdx.y * 64;
    const int tid = threadIdx.x, lane = tid & 31, w = tid >> 5;
    const int g = lane >> 2, t = lane & 3;
    const int mw = w >> 2, nq = w & 3;

    uint32_t aReg[8], bReg[4];
    #pragma unroll
    for (int i = 0; i < 8; i++) {
        int idx = 256*i + tid;
        aReg[i] = Ain[(size_t)(m0 + (idx >> 5)) * 256 + (idx & 31)];
    }
    #pragma unroll
    for (int i = 0; i < 4; i++) {
        int idx = 256*i + tid;
        bReg[i] = W[(size_t)(idx >> 5) * HALF_OUT + wc0 + (idx & 31)];
    }
    float acc[2][4] = {};

    for (int k0 = 0; k0 < 128; k0 += 32) {
        #pragma unroll
        for (int i = 0; i < 8; i++) {
            int idx = 256*i + tid;
            As[(idx >> 5)*40 + (idx & 31)] = aReg[i];
        }
        #pragma unroll
        for (int i = 0; i < 4; i++) {
            int idx = 256*i + tid;
            Bs[(idx >> 5)*36 + (idx & 31)] = bReg[i];
        }
        __syncthreads();
        if (k0 + 32 < 128) {
            #pragma unroll
            for (int i = 0; i < 8; i++) {
                int idx = 256*i + tid;
                aReg[i] = Ain[(size_t)(m0 + (idx >> 5)) * 256 + k0 + 32 + (idx & 31)];
            }
            #pragma unroll
            for (int i = 0; i < 4; i++) {
                int idx = 256*i + tid;
                bReg[i] = W[(size_t)(k0 + 32 + (idx >> 5)) * HALF_OUT + wc0 + (idx & 31)];
            }
        }
        #pragma unroll
        for (int ks = 0; ks < 2; ks++) {
            uint32_t ah[2][4], al[2][4];
            #pragma unroll
            for (int mt = 0; mt < 2; mt++) {
                int r = mw*32 + mt*16 + g;
                int d = ks*16 + 2*t;
                uint2 p0 = *(const uint2*)&As[r*40 + d];
                uint2 p1 = *(const uint2*)&As[(r+8)*40 + d];
                uint2 p2 = *(const uint2*)&As[r*40 + d + 8];
                uint2 p3 = *(const uint2*)&As[(r+8)*40 + d + 8];
                ah[mt][0] = PERM_HI(p0.x, p0.y); al[mt][0] = PERM_LO(p0.x, p0.y);
                ah[mt][1] = PERM_HI(p1.x, p1.y); al[mt][1] = PERM_LO(p1.x, p1.y);
                ah[mt][2] = PERM_HI(p2.x, p2.y); al[mt][2] = PERM_LO(p2.x, p2.y);
                ah[mt][3] = PERM_HI(p3.x, p3.y); al[mt][3] = PERM_LO(p3.x, p3.y);
            }
            {
                int nn = nq*8 + g;
                int kk = ks*16 + 2*t;
                uint32_t q0 = Bs[kk*36 + nn];
                uint32_t q1 = Bs[(kk+1)*36 + nn];
                uint32_t q2 = Bs[(kk+8)*36 + nn];
                uint32_t q3 = Bs[(kk+9)*36 + nn];
                uint32_t bfh[2] = {PERM_HI(q0, q1), PERM_HI(q2, q3)};
                uint32_t bfl[2] = {PERM_LO(q0, q1), PERM_LO(q2, q3)};
                #pragma unroll
                for (int mt = 0; mt < 2; mt++) {
                    mma_bf16(acc[mt], ah[mt], bfh);
                    mma_bf16(acc[mt], ah[mt], bfl);
                    mma_bf16(acc[mt], al[mt], bfh);
                }
            }
        }
        __syncthreads();
    }

    #pragma unroll
    for (int mt = 0; mt < 2; mt++) {
        int row = m0 + mw*32 + mt*16 + g;
        int col = nq*8 + 2*t;
        float b0 = bb[wc0 + col], b1 = bb[wc0 + col + 1];
        float v[4] = {acc[mt][0] + b0, acc[mt][1] + b1, acc[mt][2] + b0, acc[mt][3] + b1};
        #pragma unroll
        for (int j = 0; j < 4; j++) v[j] = v[j] / (1.0f + __expf(-v[j]));
        if (packed) {
            uint32_t* Yp = (uint32_t*)Yv;
            Yp[(size_t)row*DEXP + c0 + col]       = bf16_split_elem(v[0]);
            Yp[(size_t)row*DEXP + c0 + col + 1]   = bf16_split_elem(v[1]);
            Yp[(size_t)(row+8)*DEXP + c0 + col]     = bf16_split_elem(v[2]);
            Yp[(size_t)(row+8)*DEXP + c0 + col + 1] = bf16_split_elem(v[3]);
        } else {
            float* Yp = (float*)Yv;
            Yp[(size_t)row*DEXP + c0 + col]       = v[0];
            Yp[(size_t)row*DEXP + c0 + col + 1]   = v[1];
            Yp[(size_t)(row+8)*DEXP + c0 + col]     = v[2];
            Yp[(size_t)(row+8)*DEXP + c0 + col + 1] = v[3];
        }
    }
}

// ---------------- fused attention (R10 winner, unchanged) ----------------
__global__ __launch_bounds__(512, 1) void attn_kernel(
    const uint32_t* __restrict__ Qps, const uint32_t* __restrict__ Vps,
    const float* __restrict__ Uc, float* __restrict__ attn_out,
    float* __restrict__ Gout)
{
    extern __shared__ float sm[];
    float*    Sf   = sm;                              // 32*SPITCH
    uint32_t* Su   = (uint32_t*)sm;
    uint32_t* buf  = (uint32_t*)(sm + 32*SPITCH);     // 128*VPITCH >= 128*KPITCH
    uint32_t* Qb   = buf + 128*VPITCH;                // 32*QPITCH
    float*    wm   = (float*)(Qb + 32*QPITCH);        // [32 rows][16 warps]
    float*    rowInv = wm + 32*16;                    // [32]
    float*    R    = sm;                              // overlay [8][32][RPITCH]

    const int r0 = blockIdx.x * AROWS;
    const int h  = blockIdx.y, b = blockIdx.z;
    const int tid  = threadIdx.x;
    const int lane = tid & 31;
    const int w    = tid >> 5;
    const int g    = lane >> 2;
    const int t    = lane & 3;
    const float scale = 0.17677669529663687f;

    #pragma unroll
    for (int i = 0; i < 2; i++) {
        int idx = 512*i + tid;
        int r = idx >> 5, d = idx & 31;
        Qb[r*QPITCH + d] = Qps[((size_t)(r0 + r) * BSZ + b) * DQK + h*DATT + d];
    }
    uint32_t kreg[8];
    #pragma unroll
    for (int i = 0; i < 8; i++) {
        int idx = 512*i + tid;
        int key = idx >> 5, d = idx & 31;
        kreg[i] = Qps[((size_t)key * BSZ + b) * DQK + h*DATT + d];
    }
    __syncthreads();

    uint32_t qa_hi[2][2][4], qa_lo[2][2][4];
    #pragma unroll
    for (int mt = 0; mt < 2; mt++) {
        int r = mt*16 + g;
        #pragma unroll
        for (int ks = 0; ks < 2; ks++) {
            int d = ks*16 + 2*t;
            uint2 p0 = *(const uint2*)&Qb[r*QPITCH + d];
            uint2 p1 = *(const uint2*)&Qb[(r+8)*QPITCH + d];
            uint2 p2 = *(const uint2*)&Qb[r*QPITCH + d + 8];
            uint2 p3 = *(const uint2*)&Qb[(r+8)*QPITCH + d + 8];
            qa_hi[mt][ks][0] = PERM_HI(p0.x, p0.y); qa_lo[mt][ks][0] = PERM_LO(p0.x, p0.y);
            qa_hi[mt][ks][1] = PERM_HI(p1.x, p1.y); qa_lo[mt][ks][1] = PERM_LO(p1.x, p1.y);
            qa_hi[mt][ks][2] = PERM_HI(p2.x, p2.y); qa_lo[mt][ks][2] = PERM_LO(p2.x, p2.y);
            qa_hi[mt][ks][3] = PERM_HI(p3.x, p3.y); qa_lo[mt][ks][3] = PERM_LO(p3.x, p3.y);
        }
    }

    float mx[2][2] = {{-1e30f,-1e30f},{-1e30f,-1e30f}};
    for (int kt = 0; kt < 8; kt++) {
        #pragma unroll
        for (int i = 0; i < 8; i++) {
            int idx = 512*i + tid;
            buf[(idx >> 5)*KPITCH + (idx & 31)] = kreg[i];
        }
        __syncthreads();
        if (kt < 7) {
            int base = (kt + 1) * 128;
            #pragma unroll
            for (int i = 0; i < 8; i++) {
                int idx = 512*i + tid;
                int key = base + (idx >> 5), d = idx & 31;
                kreg[i] = Qps[((size_t)key * BSZ + b) * DQK + h*DATT + d];
            }
        }
        uint32_t bh[2][2], bl[2][2];
        {
            int key = w*8 + g;
            #pragma unroll
            for (int ks = 0; ks < 2; ks++) {
                int d = ks*16 + 2*t;
                uint2 p0 = *(const uint2*)&buf[key*KPITCH + d];
                uint2 p1 = *(const uint2*)&buf[key*KPITCH + d + 8];
                bh[ks][0] = PERM_HI(p0.x, p0.y); bl[ks][0] = PERM_LO(p0.x, p0.y);
                bh[ks][1] = PERM_HI(p1.x, p1.y); bl[ks][1] = PERM_LO(p1.x, p1.y);
            }
        }
        __syncthreads();
        #pragma unroll
        for (int mt = 0; mt < 2; mt++) {
            float c[4] = {0.f, 0.f, 0.f, 0.f};
            #pragma unroll
            for (int ks = 0; ks < 2; ks++) {
                mma_bf16(c, qa_hi[mt][ks], bh[ks]);
                mma_bf16(c, qa_hi[mt][ks], bl[ks]);
                mma_bf16(c, qa_lo[mt][ks], bh[ks]);
            }
            c[0] *= scale; c[1] *= scale; c[2] *= scale; c[3] *= scale;
            mx[mt][0] = fmaxf(mx[mt][0], fmaxf(c[0], c[1]));
            mx[mt][1] = fmaxf(mx[mt][1], fmaxf(c[2], c[3]));
            int row = mt*16 + g;
            int col = kt*128 + w*8 + 2*t;
            *(float2*)&Sf[row*SPITCH + col]     = make_float2(c[0], c[1]);
            *(float2*)&Sf[(row+8)*SPITCH + col] = make_float2(c[2], c[3]);
        }
    }
    #pragma unroll
    for (int mt = 0; mt < 2; mt++) {
        #pragma unroll
        for (int j = 0; j < 2; j++) {
            mx[mt][j] = fmaxf(mx[mt][j], __shfl_xor_sync(0xffffffffu, mx[mt][j], 1));
            mx[mt][j] = fmaxf(mx[mt][j], __shfl_xor_sync(0xffffffffu, mx[mt][j], 2));
        }
        if (t == 0) {
            wm[(mt*16 + g)*16 + w]     = mx[mt][0];
            wm[(mt*16 + 8 + g)*16 + w] = mx[mt][1];
        }
    }
    __syncthreads();

    uint4 vreg[4];
    #pragma unroll
    for (int i = 0; i < 4; i++) {
        int f = 512*i + tid;
        int key = f >> 4, c4 = f & 15;
        vreg[i] = *(const uint4*)&Vps[((size_t)key * BSZ + b) * DEXP + h*HDIM + c4*4];
    }

    #pragma unroll
    for (int rr = 0; rr < 2; rr++) {
        int r = w + 16*rr;
        float* row = Sf + r*SPITCH;
        uint32_t* urow = Su + r*SPITCH;
        float m = wm[r*16 + (lane & 15)];
        #pragma unroll
        for (int o = 8; o; o >>= 1) m = fmaxf(m, __shfl_xor_sync(0xffffffffu, m, o));
        float s = 0.f;
        #pragma unroll 4
        for (int i = 0; i < 16; i++) {
            int k = 2*lane + 64*i;
            float2 x = *(const float2*)&row[k];
            float e0 = __expf(x.x - m), e1 = __expf(x.y - m);
            s += e0 + e1;
            uint2 pk = make_uint2(bf16_split_elem(e0), bf16_split_elem(e1));
            *(uint2*)&urow[k] = pk;
        }
        #pragma unroll
        for (int o = 16; o; o >>= 1) s += __shfl_xor_sync(0xffffffffu, s, o);
        float inv = 1.0f / s;
        if (lane == 0) rowInv[r] = inv;
        __syncwarp();
        float* gp = attn_out ? attn_out + (((size_t)(b*NHEAD + h) * LL + (r0 + r)) * LL) : nullptr;
        if (gp) {
            #pragma unroll 4
            for (int i = 0; i < 16; i++) {
                int k = 2*lane + 64*i;
                uint2 p = *(const uint2*)&urow[k];
                *(float2*)&gp[k] = make_float2(bf16_unsplit(p.x) * inv, bf16_unsplit(p.y) * inv);
            }
        }
    }
    __syncthreads();

    const int ks = w >> 1;
    const int nh = w & 1;
    float cav[2][4][4] = {};
    for (int vt = 0; vt < 8; vt++) {
        #pragma unroll
        for (int i = 0; i < 4; i++) {
            int f = 512*i + tid;
            int key = f >> 4, c4 = f & 15;
            *(uint4*)&buf[key*VPITCH + c4*4] = vreg[i];
        }
        __syncthreads();
        if (vt < 7) {
            int base = (vt + 1) * 128;
            #pragma unroll
            for (int i = 0; i < 4; i++) {
                int f = 512*i + tid;
                int key = base + (f >> 4), c4 = f & 15;
                vreg[i] = *(const uint4*)&Vps[((size_t)key * BSZ + b) * DEXP + h*HDIM + c4*4];
            }
        }
        uint32_t ah[2][4], al[2][4];
        #pragma unroll
        for (int mt = 0; mt < 2; mt++) {
            int r = mt*16 + g;
            int d = vt*128 + ks*16 + 2*t;
            uint2 p0 = *(const uint2*)&Su[r*SPITCH + d];
            uint2 p1 = *(const uint2*)&Su[(r+8)*SPITCH + d];
            uint2 p2 = *(const uint2*)&Su[r*SPITCH + d + 8];
            uint2 p3 = *(const uint2*)&Su[(r+8)*SPITCH + d + 8];
            ah[mt][0] = PERM_HI(p0.x, p0.y); al[mt][0] = PERM_LO(p0.x, p0.y);
            ah[mt][1] = PERM_HI(p1.x, p1.y); al[mt][1] = PERM_LO(p1.x, p1.y);
            ah[mt][2] = PERM_HI(p2.x, p2.y); al[mt][2] = PERM_LO(p2.x, p2.y);
            ah[mt][3] = PERM_HI(p3.x, p3.y); al[mt][3] = PERM_LO(p3.x, p3.y);
        }
        #pragma unroll
        for (int nt = 0; nt < 4; nt++) {
            int nn = nh*32 + nt*8 + g;
            int kk = ks*16 + 2*t;
            uint32_t q0 = buf[kk*VPITCH + nn];
            uint32_t q1 = buf[(kk+1)*VPITCH + nn];
            uint32_t q2 = buf[(kk+8)*VPITCH + nn];
            uint32_t q3 = buf[(kk+9)*VPITCH + nn];
            uint32_t bfh[2] = {PERM_HI(q0, q1), PERM_HI(q2, q3)};
            uint32_t bfl[2] = {PERM_LO(q0, q1), PERM_LO(q2, q3)};
            #pragma unroll
            for (int mt = 0; mt < 2; mt++) {
                mma_bf16(cav[mt][nt], ah[mt], bfh);
                mma_bf16(cav[mt][nt], ah[mt], bfl);
                mma_bf16(cav[mt][nt], al[mt], bfh);
            }
        }
        __syncthreads();
    }

    #pragma unroll
    for (int mt = 0; mt < 2; mt++) {
        int row = mt*16 + g;
        #pragma unroll
        for (int nt = 0; nt < 4; nt++) {
            int col = nh*32 + nt*8 + 2*t;
            *(float2*)&R[(ks*32 + row)*RPITCH + col]     = make_float2(cav[mt][nt][0], cav[mt][nt][1]);
            *(float2*)&R[(ks*32 + row + 8)*RPITCH + col] = make_float2(cav[mt][nt][2], cav[mt][nt][3]);
        }
    }
    __syncthreads();

    {
        int rr = tid >> 4;
        int c  = 2*(tid & 15);
        float2 s  = make_float2(0.f, 0.f);
        float2 s2 = make_float2(0.f, 0.f);
        #pragma unroll
        for (int kq = 0; kq < 8; kq++) {
            float2 p  = *(const float2*)&R[(kq*32 + rr)*RPITCH + c];
            float2 p2 = *(const float2*)&R[(kq*32 + rr)*RPITCH + c + 32];
            s.x += p.x;  s.y += p.y;
            s2.x += p2.x; s2.y += p2.y;
        }
        float inv = rowInv[rr];
        size_t gb = ((size_t)(r0 + rr) * BSZ + b) * DEXP + h*HDIM;
        float2 u  = *(const float2*)&Uc[gb + c];
        *(float2*)&Gout[gb + c] = make_float2(s.x*inv*u.x, s.y*inv*u.y);
        float2 u2 = *(const float2*)&Uc[gb + c + 32];
        *(float2*)&Gout[gb + c + 32] = make_float2(s2.x*inv*u2.x, s2.y*inv*u2.y);
    }
}

// ---------------- depthwise 5x5 conv, row-tiled, packed output ----------------
__global__ __launch_bounds__(256) void dwconv_kernel(
    const float* __restrict__ X, const float* __restrict__ Wc, uint32_t* __restrict__ Yp)
{
    extern __shared__ float sm[];
    float* xs = sm;              // [12*32][33]
    float* ws = sm + 384*33;     // [32][25]
    const int c0 = blockIdx.x * 32;
    const int r0 = blockIdx.y * 8;
    const int b  = blockIdx.z;
    const int tid = threadIdx.x;

    #pragma unroll
    for (int i = 0; i < 48; i++) {
        int idx = tid + 256*i;
        int lp = idx >> 5, c = idx & 31;
        int gr = r0 - 2 + (lp >> 5);
        int j  = lp & 31;
        float v = 0.f;
        if (gr >= 0 && gr < 32)
            v = X[((size_t)(gr*32 + j) * BSZ + b) * DEXP + c0 + c];
        xs[lp*33 + c] = v;
    }
    for (int idx = tid; idx < 32*25; idx += 256) {
        int c = idx / 25, tt = idx % 25;
        ws[c*25 + tt] = Wc[(size_t)(c0 + c) * 25 + tt];
    }
    __syncthreads();

    const int c = tid & 31, pr = tid >> 5;
    for (int s = 0; s < 32; s++) {
        int pos = pr + 8*s;
        int rl = pos >> 5, j = pos & 31;
        float acc = 0.f;
        #pragma unroll
        for (int di = 0; di < 5; di++) {
            int li = rl + di;
            #pragma unroll
            for (int dj = 0; dj < 5; dj++) {
                int jj = j + dj - 2;
                if (jj < 0 || jj >= 32) continue;
                acc += xs[(li*32 + jj)*33 + c] * ws[c*25 + di*5 + dj];
            }
        }
        Yp[((size_t)((r0 + rl)*32 + j) * BSZ + b) * DEXP + c0 + c] = bf16_split_elem(acc);
    }
}

// ---------------- launch ----------------
extern "C" void kernel_launch(void* const* d_in, const int* in_sizes, int n_in,
                              void* d_out, int out_size)
{
    const float* Q   = (const float*)d_in[0];
    const float* V   = (const float*)d_in[2];
    const float* U   = (const float*)d_in[3];
    const float* Wqk = (const float*)d_in[4];
    const float* bqk = (const float*)d_in[5];
    const float* Wv1 = (const float*)d_in[6];
    const float* bv1 = (const float*)d_in[7];
    const float* Wv2 = (const float*)d_in[8];
    const float* bv2 = (const float*)d_in[9];
    const float* Wu1 = (const float*)d_in[10];
    const float* bu1 = (const float*)d_in[11];
    const float* Wu2 = (const float*)d_in[12];
    const float* bu2 = (const float*)d_in[13];
    const float* Wcv = (const float*)d_in[14];
    const float* Wp  = (const float*)d_in[15];
    const float* bp  = (const float*)d_in[16];

    float* out  = (float*)d_out;
    float* attn = (out_size > MROWS*DQK) ? out + (size_t)MROWS*DQK : nullptr;

    uint32_t *Qps, *Vps, *Yp, *Qin, *Vin, *Uin, *pWqk, *pWv1, *pWv2, *pWu1, *pWu2, *pWp;
    float *Uc, *G;
    cudaGetSymbolAddress((void**)&Qps, g_Qps);
    cudaGetSymbolAddress((void**)&Vps, g_Vps);
    cudaGetSymbolAddress((void**)&Uc,  g_Uc);
    cudaGetSymbolAddress((void**)&G,   g_G);
    cudaGetSymbolAddress((void**)&Yp,  g_Yp);
    cudaGetSymbolAddress((void**)&Qin, g_Qin);
    cudaGetSymbolAddress((void**)&Vin, g_Vin);
    cudaGetSymbolAddress((void**)&Uin, g_Uin);
    cudaGetSymbolAddress((void**)&pWqk, g_Wqk);
    cudaGetSymbolAddress((void**)&pWv1, g_Wv1);
    cudaGetSymbolAddress((void**)&pWv2, g_Wv2);
    cudaGetSymbolAddress((void**)&pWu1, g_Wu1);
    cudaGetSymbolAddress((void**)&pWu2, g_Wu2);
    cudaGetSymbolAddress((void**)&pWp, g_Wpp);

    const size_t ATTN_SMEM = (size_t)(32*SPITCH + 128*VPITCH + 32*QPITCH + 32*16 + 32) * 4; // ~174 KB
    const size_t CONV_SMEM = (size_t)(384*33 + 32*25) * sizeof(float);
    cudaFuncSetAttribute(attn_kernel,   cudaFuncAttributeMaxDynamicSharedMemorySize, (int)ATTN_SMEM);
    cudaFuncSetAttribute(dwconv_kernel, cudaFuncAttributeMaxDynamicSharedMemorySize, (int)CONV_SMEM);

    // 0) pack inputs + weights
    {
        pack_kernel<<<(MROWS*DQK + 255)/256, 256>>>(Q,   Qin,  MROWS*DQK);
        pack_kernel<<<(MROWS*DQK + 255)/256, 256>>>(V,   Vin,  MROWS*DQK);
        pack_kernel<<<(MROWS*DQK + 255)/256, 256>>>(U,   Uin,  MROWS*DQK);
        pack_kernel<<<(DQK*DQK + 255)/256, 256>>>(Wqk, pWqk, DQK*DQK);
        pack_kernel<<<(128*HALF_OUT + 255)/256, 256>>>(Wv1, pWv1, 128*HALF_OUT);
        pack_kernel<<<(128*HALF_OUT + 255)/256, 256>>>(Wv2, pWv2, 128*HALF_OUT);
        pack_kernel<<<(128*HALF_OUT + 255)/256, 256>>>(Wu1, pWu1, 128*HALF_OUT);
        pack_kernel<<<(128*HALF_OUT + 255)/256, 256>>>(Wu2, pWu2, 128*HALF_OUT);
        pack_kernel<<<(DEXP*DQK + 255)/256, 256>>>(Wp,  pWp,  DEXP*DQK);
    }
    // 1) Qp = Q @ Wqk + bqk -> packed u32
    {
        dim3 grid(DQK/64, MROWS/64);
        mma_gemm_kernel<<<grid, 256>>>(Qin, pWqk, bqk, Qps, MROWS, DQK, DQK, 1);
    }
    // 2) Vc packed, Uc fp32
    {
        dim3 grid(16, MROWS/64);
        mma_gated_kernel<<<grid, 256>>>(Vin, pWv1, bv1, pWv2, bv2, Vps, 1);
        mma_gated_kernel<<<grid, 256>>>(Uin, pWu1, bu1, pWu2, bu2, Uc, 0);
    }
    // 3) attention
    {
        dim3 grid(LL/AROWS, NHEAD, BSZ);
        attn_kernel<<<grid, 512, ATTN_SMEM>>>(Qps, Vps, Uc, attn, G);
    }
    // 4) depthwise conv -> packed Y
    {
        dim3 grid(16, 4, BSZ);
        dwconv_kernel<<<grid, 256, CONV_SMEM>>>(G, Wcv, Yp);
    }
    // 5) outputs = Y @ Wp + bp
    {
        dim3 grid(DQK/64, MROWS/64);
        mma_gemm_kernel<<<grid, 256>>>(Yp, pWp, bp, out, MROWS, DQK, DEXP, 0);
    }
}

// round 14
// speedup vs baseline: 1.0526x; 1.0526x over previous
#include <cuda_runtime.h>
#include <cuda_bf16.h>
#include <math.h>
#include <stdint.h>

#define LL    1024
#define BSZ   8
#define DQK   256
#define DEXP  512
#define NHEAD 8
#define HDIM  64
#define DATT  32
#define MROWS (LL*BSZ)   // 8192
#define HALF_OUT 256
#define SPITCH 1032
#define KPITCH 40
#define QPITCH 40
#define VPITCH 68
#define RPITCH 72
#define AROWS  32

// ---------------- scratch ----------------
__device__ __align__(256) uint32_t g_Qps[MROWS*DQK];   // packed Qp (post-GEMM)
__device__ __align__(256) uint32_t g_Vps[MROWS*DEXP];  // packed Vc
__device__ __align__(256) float    g_Uc [MROWS*DEXP];
__device__ __align__(256) float    g_G  [MROWS*DEXP];
__device__ __align__(256) uint32_t g_Yp [MROWS*DEXP];  // packed conv output
// packed inputs/weights
__device__ __align__(256) uint32_t g_Qin[MROWS*DQK];
__device__ __align__(256) uint32_t g_Vin[MROWS*DQK];
__device__ __align__(256) uint32_t g_Uin[MROWS*DQK];
__device__ __align__(256) uint32_t g_Wqk[DQK*DQK];
__device__ __align__(256) uint32_t g_Wv1[128*HALF_OUT];
__device__ __align__(256) uint32_t g_Wv2[128*HALF_OUT];
__device__ __align__(256) uint32_t g_Wu1[128*HALF_OUT];
__device__ __align__(256) uint32_t g_Wu2[128*HALF_OUT];
__device__ __align__(256) uint32_t g_Wpp[DEXP*DQK];

// ---------------- helpers ----------------
__device__ __forceinline__ uint32_t bf16_split_elem(float x) {
    __nv_bfloat16 hb = __float2bfloat16_rn(x);
    float hf = __bfloat162float(hb);
    __nv_bfloat16 lb = __float2bfloat16_rn(x - hf);
    return ((uint32_t)__bfloat16_as_ushort(lb) << 16) | (uint32_t)__bfloat16_as_ushort(hb);
}
__device__ __forceinline__ float bf16_unsplit(uint32_t p) {
    return __uint_as_float(p << 16) + __uint_as_float(p & 0xffff0000u);
}

__device__ __forceinline__ void mma_bf16(float* c, const uint32_t* a, const uint32_t* b) {
    asm volatile(
        "mma.sync.aligned.m16n8k16.row.col.f32.bf16.bf16.f32 "
        "{%0,%1,%2,%3},{%4,%5,%6,%7},{%8,%9},{%0,%1,%2,%3};"
        : "+f"(c[0]), "+f"(c[1]), "+f"(c[2]), "+f"(c[3])
        : "r"(a[0]), "r"(a[1]), "r"(a[2]), "r"(a[3]), "r"(b[0]), "r"(b[1]));
}

#define PERM_HI(p0, p1) __byte_perm((p0), (p1), 0x5410)
#define PERM_LO(p0, p1) __byte_perm((p0), (p1), 0x7632)

// ---------------- fused pack: all 9 tensors in ONE launch, uint4-vectorized ----------------
#define SZ_IN   (MROWS*DQK)        // 2097152 (Q, V, U each)
#define SZ_WQK  (DQK*DQK)          // 65536
#define SZ_WH   (128*HALF_OUT)     // 32768 (x4)
#define SZ_WP   (DEXP*DQK)         // 131072
#define PACK_TOTAL (3*SZ_IN + SZ_WQK + 4*SZ_WH + SZ_WP)   // 6619136 floats
#define PACK_V4    (PACK_TOTAL/4)

__device__ __forceinline__ void pack4(const float* __restrict__ s, uint32_t* __restrict__ d, int e) {
    float4 x = *(const float4*)&s[e];
    uint4 y;
    y.x = bf16_split_elem(x.x); y.y = bf16_split_elem(x.y);
    y.z = bf16_split_elem(x.z); y.w = bf16_split_elem(x.w);
    *(uint4*)&d[e] = y;
}

__global__ __launch_bounds__(256) void pack_all_kernel(
    const float* __restrict__ Q, const float* __restrict__ V, const float* __restrict__ U,
    const float* __restrict__ Wqk,
    const float* __restrict__ Wv1, const float* __restrict__ Wv2,
    const float* __restrict__ Wu1, const float* __restrict__ Wu2,
    const float* __restrict__ Wp)
{
    for (int v = blockIdx.x * 256 + threadIdx.x; v < PACK_V4; v += gridDim.x * 256) {
        int e = v * 4;
        if (e < SZ_IN)                    { pack4(Q,   g_Qin, e); continue; }
        e -= SZ_IN;
        if (e < SZ_IN)                    { pack4(V,   g_Vin, e); continue; }
        e -= SZ_IN;
        if (e < SZ_IN)                    { pack4(U,   g_Uin, e); continue; }
        e -= SZ_IN;
        if (e < SZ_WQK)                   { pack4(Wqk, g_Wqk, e); continue; }
        e -= SZ_WQK;
        if (e < SZ_WH)                    { pack4(Wv1, g_Wv1, e); continue; }
        e -= SZ_WH;
        if (e < SZ_WH)                    { pack4(Wv2, g_Wv2, e); continue; }
        e -= SZ_WH;
        if (e < SZ_WH)                    { pack4(Wu1, g_Wu1, e); continue; }
        e -= SZ_WH;
        if (e < SZ_WH)                    { pack4(Wu2, g_Wu2, e); continue; }
        e -= SZ_WH;
        pack4(Wp, g_Wpp, e);
    }
}

// ---------------- tensor-core GEMM + bias, PACKED operands ----------------
__global__ __launch_bounds__(256) void mma_gemm_kernel(
    const uint32_t* __restrict__ A, const uint32_t* __restrict__ B,
    const float* __restrict__ bias, void* __restrict__ Cv,
    int M, int N, int K, int mode)
{
    __shared__ uint32_t As[64*40];
    __shared__ uint32_t Bs[32*68];
    const int m0 = blockIdx.y * 64, n0 = blockIdx.x * 64;
    const int tid = threadIdx.x, lane = tid & 31, w = tid >> 5;
    const int g = lane >> 2, t = lane & 3;
    const int mw = w >> 2, nq = w & 3;

    uint32_t aReg[8], bReg[8];
    #pragma unroll
    for (int i = 0; i < 8; i++) {
        int idx = 256*i + tid;
        aReg[i] = A[(size_t)(m0 + (idx >> 5)) * K + (idx & 31)];
        bReg[i] = B[(size_t)(idx >> 6) * N + n0 + (idx & 63)];
    }
    float acc[2][2][4] = {};

    for (int k0 = 0; k0 < K; k0 += 32) {
        #pragma unroll
        for (int i = 0; i < 8; i++) {
            int idx = 256*i + tid;
            As[(idx >> 5)*40 + (idx & 31)] = aReg[i];
            Bs[(idx >> 6)*68 + (idx & 63)] = bReg[i];
        }
        __syncthreads();
        if (k0 + 32 < K) {
            #pragma unroll
            for (int i = 0; i < 8; i++) {
                int idx = 256*i + tid;
                aReg[i] = A[(size_t)(m0 + (idx >> 5)) * K + k0 + 32 + (idx & 31)];
                bReg[i] = B[(size_t)(k0 + 32 + (idx >> 6)) * N + n0 + (idx & 63)];
            }
        }
        #pragma unroll
        for (int ks = 0; ks < 2; ks++) {
            uint32_t ah[2][4], al[2][4];
            #pragma unroll
            for (int mt = 0; mt < 2; mt++) {
                int r = mw*32 + mt*16 + g;
                int d = ks*16 + 2*t;
                uint2 p0 = *(const uint2*)&As[r*40 + d];
                uint2 p1 = *(const uint2*)&As[(r+8)*40 + d];
                uint2 p2 = *(const uint2*)&As[r*40 + d + 8];
                uint2 p3 = *(const uint2*)&As[(r+8)*40 + d + 8];
                ah[mt][0] = PERM_HI(p0.x, p0.y); al[mt][0] = PERM_LO(p0.x, p0.y);
                ah[mt][1] = PERM_HI(p1.x, p1.y); al[mt][1] = PERM_LO(p1.x, p1.y);
                ah[mt][2] = PERM_HI(p2.x, p2.y); al[mt][2] = PERM_LO(p2.x, p2.y);
                ah[mt][3] = PERM_HI(p3.x, p3.y); al[mt][3] = PERM_LO(p3.x, p3.y);
            }
            #pragma unroll
            for (int nt = 0; nt < 2; nt++) {
                int nn = nq*16 + nt*8 + g;
                int kk = ks*16 + 2*t;
                uint32_t q0 = Bs[kk*68 + nn];
                uint32_t q1 = Bs[(kk+1)*68 + nn];
                uint32_t q2 = Bs[(kk+8)*68 + nn];
                uint32_t q3 = Bs[(kk+9)*68 + nn];
                uint32_t bfh[2] = {PERM_HI(q0, q1), PERM_HI(q2, q3)};
                uint32_t bfl[2] = {PERM_LO(q0, q1), PERM_LO(q2, q3)};
                #pragma unroll
                for (int mt = 0; mt < 2; mt++) {
                    mma_bf16(acc[mt][nt], ah[mt], bfh);
                    mma_bf16(acc[mt][nt], ah[mt], bfl);
                    mma_bf16(acc[mt][nt], al[mt], bfh);
                }
            }
        }
        __syncthreads();
    }

    #pragma unroll
    for (int mt = 0; mt < 2; mt++) {
        int row = m0 + mw*32 + mt*16 + g;
        #pragma unroll
        for (int nt = 0; nt < 2; nt++) {
            int col = n0 + nq*16 + nt*8 + 2*t;
            float b0 = bias[col], b1 = bias[col+1];
            float v0 = acc[mt][nt][0] + b0, v1 = acc[mt][nt][1] + b1;
            float v2 = acc[mt][nt][2] + b0, v3 = acc[mt][nt][3] + b1;
            if (mode == 0) {
                float* C = (float*)Cv;
                C[(size_t)row*N + col]       = v0;
                C[(size_t)row*N + col + 1]   = v1;
                C[(size_t)(row+8)*N + col]     = v2;
                C[(size_t)(row+8)*N + col + 1] = v3;
            } else {
                uint32_t* C = (uint32_t*)Cv;
                C[(size_t)row*N + col]       = bf16_split_elem(v0);
                C[(size_t)row*N + col + 1]   = bf16_split_elem(v1);
                C[(size_t)(row+8)*N + col]     = bf16_split_elem(v2);
                C[(size_t)(row+8)*N + col + 1] = bf16_split_elem(v3);
            }
        }
    }
}

// ---------------- tensor-core gated half-projection + SiLU, PACKED operands ----------------
__global__ __launch_bounds__(256) void mma_gated_kernel(
    const uint32_t* __restrict__ X,
    const uint32_t* __restrict__ W1, const float* __restrict__ b1,
    const uint32_t* __restrict__ W2, const float* __restrict__ b2,
    void* __restrict__ Yv, int packed)
{
    __shared__ uint32_t As[64*40];
    __shared__ uint32_t Bs[32*36];
    const int c0   = blockIdx.x * 32;
    const int head = c0 >> 6;
    const int is2  = (c0 >> 5) & 1;
    const uint32_t* W  = is2 ? W2 : W1;
    const float* bb = is2 ? b2 : b1;
    const int wc0 = head * 32;
    const uint32_t* Ain = X + (is2 ? 128 : 0);
    const int m0 = blockIdx.y * 64;
    const int tid = threadIdx.x, lane = tid & 31, w = tid >> 5;
    const int g = lane >> 2, t = lane & 3;
    const int mw = w >> 2, nq = w & 3;

    uint32_t aReg[8], bReg[4];
    #pragma unroll
    for (int i = 0; i < 8; i++) {
        int idx = 256*i + tid;
        aReg[i] = Ain[(size_t)(m0 + (idx >> 5)) * 256 + (idx & 31)];
    }
    #pragma unroll
    for (int i = 0; i < 4; i++) {
        int idx = 256*i + tid;
        bReg[i] = W[(size_t)(idx >> 5) * HALF_OUT + wc0 + (idx & 31)];
    }
    float acc[2][4] = {};

    for (int k0 = 0; k0 < 128; k0 += 32) {
        #pragma unroll
        for (int i = 0; i < 8; i++) {
            int idx = 256*i + tid;
            As[(idx >> 5)*40 + (idx & 31)] = aReg[i];
        }
        #pragma unroll
        for (int i = 0; i < 4; i++) {
            int idx = 256*i + tid;
            Bs[(idx >> 5)*36 + (idx & 31)] = bReg[i];
        }
        __syncthreads();
        if (k0 + 32 < 128) {
            #pragma unroll
            for (int i = 0; i < 8; i++) {
                int idx = 256*i + tid;
                aReg[i] = Ain[(size_t)(m0 + (idx >> 5)) * 256 + k0 + 32 + (idx & 31)];
            }
            #pragma unroll
            for (int i = 0; i < 4; i++) {
                int idx = 256*i + tid;
                bReg[i] = W[(size_t)(k0 + 32 + (idx >> 5)) * HALF_OUT + wc0 + (idx & 31)];
            }
        }
        #pragma unroll
        for (int ks = 0; ks < 2; ks++) {
            uint32_t ah[2][4], al[2][4];
            #pragma unroll
            for (int mt = 0; mt < 2; mt++) {
                int r = mw*32 + mt*16 + g;
                int d = ks*16 + 2*t;
                uint2 p0 = *(const uint2*)&As[r*40 + d];
                uint2 p1 = *(const uint2*)&As[(r+8)*40 + d];
                uint2 p2 = *(const uint2*)&As[r*40 + d + 8];
                uint2 p3 = *(const uint2*)&As[(r+8)*40 + d + 8];
                ah[mt][0] = PERM_HI(p0.x, p0.y); al[mt][0] = PERM_LO(p0.x, p0.y);
                ah[mt][1] = PERM_HI(p1.x, p1.y); al[mt][1] = PERM_LO(p1.x, p1.y);
                ah[mt][2] = PERM_HI(p2.x, p2.y); al[mt][2] = PERM_LO(p2.x, p2.y);
                ah[mt][3] = PERM_HI(p3.x, p3.y); al[mt][3] = PERM_LO(p3.x, p3.y);
            }
            {
                int nn = nq*8 + g;
                int kk = ks*16 + 2*t;
                uint32_t q0 = Bs[kk*36 + nn];
                uint32_t q1 = Bs[(kk+1)*36 + nn];
                uint32_t q2 = Bs[(kk+8)*36 + nn];
                uint32_t q3 = Bs[(kk+9)*36 + nn];
                uint32_t bfh[2] = {PERM_HI(q0, q1), PERM_HI(q2, q3)};
                uint32_t bfl[2] = {PERM_LO(q0, q1), PERM_LO(q2, q3)};
                #pragma unroll
                for (int mt = 0; mt < 2; mt++) {
                    mma_bf16(acc[mt], ah[mt], bfh);
                    mma_bf16(acc[mt], ah[mt], bfl);
                    mma_bf16(acc[mt], al[mt], bfh);
                }
            }
        }
        __syncthreads();
    }

    #pragma unroll
    for (int mt = 0; mt < 2; mt++) {
        int row = m0 + mw*32 + mt*16 + g;
        int col = nq*8 + 2*t;
        float b0 = bb[wc0 + col], b1 = bb[wc0 + col + 1];
        float v[4] = {acc[mt][0] + b0, acc[mt][1] + b1, acc[mt][2] + b0, acc[mt][3] + b1};
        #pragma unroll
        for (int j = 0; j < 4; j++) v[j] = v[j] / (1.0f + __expf(-v[j]));
        if (packed) {
            uint32_t* Yp = (uint32_t*)Yv;
            Yp[(size_t)row*DEXP + c0 + col]       = bf16_split_elem(v[0]);
            Yp[(size_t)row*DEXP + c0 + col + 1]   = bf16_split_elem(v[1]);
            Yp[(size_t)(row+8)*DEXP + c0 + col]     = bf16_split_elem(v[2]);
            Yp[(size_t)(row+8)*DEXP + c0 + col + 1] = bf16_split_elem(v[3]);
        } else {
            float* Yp = (float*)Yv;
            Yp[(size_t)row*DEXP + c0 + col]       = v[0];
            Yp[(size_t)row*DEXP + c0 + col + 1]   = v[1];
            Yp[(size_t)(row+8)*DEXP + c0 + col]     = v[2];
            Yp[(size_t)(row+8)*DEXP + c0 + col + 1] = v[3];
        }
    }
}

// ---------------- fused attention (R10 winner, unchanged) ----------------
__global__ __launch_bounds__(512, 1) void attn_kernel(
    const uint32_t* __restrict__ Qps, const uint32_t* __restrict__ Vps,
    const float* __restrict__ Uc, float* __restrict__ attn_out,
    float* __restrict__ Gout)
{
    extern __shared__ float sm[];
    float*    Sf   = sm;
    uint32_t* Su   = (uint32_t*)sm;
    uint32_t* buf  = (uint32_t*)(sm + 32*SPITCH);
    uint32_t* Qb   = buf + 128*VPITCH;
    float*    wm   = (float*)(Qb + 32*QPITCH);
    float*    rowInv = wm + 32*16;
    float*    R    = sm;

    const int r0 = blockIdx.x * AROWS;
    const int h  = blockIdx.y, b = blockIdx.z;
    const int tid  = threadIdx.x;
    const int lane = tid & 31;
    const int w    = tid >> 5;
    const int g    = lane >> 2;
    const int t    = lane & 3;
    const float scale = 0.17677669529663687f;

    #pragma unroll
    for (int i = 0; i < 2; i++) {
        int idx = 512*i + tid;
        int r = idx >> 5, d = idx & 31;
        Qb[r*QPITCH + d] = Qps[((size_t)(r0 + r) * BSZ + b) * DQK + h*DATT + d];
    }
    uint32_t kreg[8];
    #pragma unroll
    for (int i = 0; i < 8; i++) {
        int idx = 512*i + tid;
        int key = idx >> 5, d = idx & 31;
        kreg[i] = Qps[((size_t)key * BSZ + b) * DQK + h*DATT + d];
    }
    __syncthreads();

    uint32_t qa_hi[2][2][4], qa_lo[2][2][4];
    #pragma unroll
    for (int mt = 0; mt < 2; mt++) {
        int r = mt*16 + g;
        #pragma unroll
        for (int ks = 0; ks < 2; ks++) {
            int d = ks*16 + 2*t;
            uint2 p0 = *(const uint2*)&Qb[r*QPITCH + d];
            uint2 p1 = *(const uint2*)&Qb[(r+8)*QPITCH + d];
            uint2 p2 = *(const uint2*)&Qb[r*QPITCH + d + 8];
            uint2 p3 = *(const uint2*)&Qb[(r+8)*QPITCH + d + 8];
            qa_hi[mt][ks][0] = PERM_HI(p0.x, p0.y); qa_lo[mt][ks][0] = PERM_LO(p0.x, p0.y);
            qa_hi[mt][ks][1] = PERM_HI(p1.x, p1.y); qa_lo[mt][ks][1] = PERM_LO(p1.x, p1.y);
            qa_hi[mt][ks][2] = PERM_HI(p2.x, p2.y); qa_lo[mt][ks][2] = PERM_LO(p2.x, p2.y);
            qa_hi[mt][ks][3] = PERM_HI(p3.x, p3.y); qa_lo[mt][ks][3] = PERM_LO(p3.x, p3.y);
        }
    }

    float mx[2][2] = {{-1e30f,-1e30f},{-1e30f,-1e30f}};
    for (int kt = 0; kt < 8; kt++) {
        #pragma unroll
        for (int i = 0; i < 8; i++) {
            int idx = 512*i + tid;
            buf[(idx >> 5)*KPITCH + (idx & 31)] = kreg[i];
        }
        __syncthreads();
        if (kt < 7) {
            int base = (kt + 1) * 128;
            #pragma unroll
            for (int i = 0; i < 8; i++) {
                int idx = 512*i + tid;
                int key = base + (idx >> 5), d = idx & 31;
                kreg[i] = Qps[((size_t)key * BSZ + b) * DQK + h*DATT + d];
            }
        }
        uint32_t bh[2][2], bl[2][2];
        {
            int key = w*8 + g;
            #pragma unroll
            for (int ks = 0; ks < 2; ks++) {
                int d = ks*16 + 2*t;
                uint2 p0 = *(const uint2*)&buf[key*KPITCH + d];
                uint2 p1 = *(const uint2*)&buf[key*KPITCH + d + 8];
                bh[ks][0] = PERM_HI(p0.x, p0.y); bl[ks][0] = PERM_LO(p0.x, p0.y);
                bh[ks][1] = PERM_HI(p1.x, p1.y); bl[ks][1] = PERM_LO(p1.x, p1.y);
            }
        }
        __syncthreads();
        #pragma unroll
        for (int mt = 0; mt < 2; mt++) {
            float c[4] = {0.f, 0.f, 0.f, 0.f};
            #pragma unroll
            for (int ks = 0; ks < 2; ks++) {
                mma_bf16(c, qa_hi[mt][ks], bh[ks]);
                mma_bf16(c, qa_hi[mt][ks], bl[ks]);
                mma_bf16(c, qa_lo[mt][ks], bh[ks]);
            }
            c[0] *= scale; c[1] *= scale; c[2] *= scale; c[3] *= scale;
            mx[mt][0] = fmaxf(mx[mt][0], fmaxf(c[0], c[1]));
            mx[mt][1] = fmaxf(mx[mt][1], fmaxf(c[2], c[3]));
            int row = mt*16 + g;
            int col = kt*128 + w*8 + 2*t;
            *(float2*)&Sf[row*SPITCH + col]     = make_float2(c[0], c[1]);
            *(float2*)&Sf[(row+8)*SPITCH + col] = make_float2(c[2], c[3]);
        }
    }
    #pragma unroll
    for (int mt = 0; mt < 2; mt++) {
        #pragma unroll
        for (int j = 0; j < 2; j++) {
            mx[mt][j] = fmaxf(mx[mt][j], __shfl_xor_sync(0xffffffffu, mx[mt][j], 1));
            mx[mt][j] = fmaxf(mx[mt][j], __shfl_xor_sync(0xffffffffu, mx[mt][j], 2));
        }
        if (t == 0) {
            wm[(mt*16 + g)*16 + w]     = mx[mt][0];
            wm[(mt*16 + 8 + g)*16 + w] = mx[mt][1];
        }
    }
    __syncthreads();

    uint4 vreg[4];
    #pragma unroll
    for (int i = 0; i < 4; i++) {
        int f = 512*i + tid;
        int key = f >> 4, c4 = f & 15;
        vreg[i] = *(const uint4*)&Vps[((size_t)key * BSZ + b) * DEXP + h*HDIM + c4*4];
    }

    #pragma unroll
    for (int rr = 0; rr < 2; rr++) {
        int r = w + 16*rr;
        float* row = Sf + r*SPITCH;
        uint32_t* urow = Su + r*SPITCH;
        float m = wm[r*16 + (lane & 15)];
        #pragma unroll
        for (int o = 8; o; o >>= 1) m = fmaxf(m, __shfl_xor_sync(0xffffffffu, m, o));
        float s = 0.f;
        #pragma unroll 4
        for (int i = 0; i < 16; i++) {
            int k = 2*lane + 64*i;
            float2 x = *(const float2*)&row[k];
            float e0 = __expf(x.x - m), e1 = __expf(x.y - m);
            s += e0 + e1;
            uint2 pk = make_uint2(bf16_split_elem(e0), bf16_split_elem(e1));
            *(uint2*)&urow[k] = pk;
        }
        #pragma unroll
        for (int o = 16; o; o >>= 1) s += __shfl_xor_sync(0xffffffffu, s, o);
        float inv = 1.0f / s;
        if (lane == 0) rowInv[r] = inv;
        __syncwarp();
        float* gp = attn_out ? attn_out + (((size_t)(b*NHEAD + h) * LL + (r0 + r)) * LL) : nullptr;
        if (gp) {
            #pragma unroll 4
            for (int i = 0; i < 16; i++) {
                int k = 2*lane + 64*i;
                uint2 p = *(const uint2*)&urow[k];
                *(float2*)&gp[k] = make_float2(bf16_unsplit(p.x) * inv, bf16_unsplit(p.y) * inv);
            }
        }
    }
    __syncthreads();

    const int ks = w >> 1;
    const int nh = w & 1;
    float cav[2][4][4] = {};
    for (int vt = 0; vt < 8; vt++) {
        #pragma unroll
        for (int i = 0; i < 4; i++) {
            int f = 512*i + tid;
            int key = f >> 4, c4 = f & 15;
            *(uint4*)&buf[key*VPITCH + c4*4] = vreg[i];
        }
        __syncthreads();
        if (vt < 7) {
            int base = (vt + 1) * 128;
            #pragma unroll
            for (int i = 0; i < 4; i++) {
                int f = 512*i + tid;
                int key = base + (f >> 4), c4 = f & 15;
                vreg[i] = *(const uint4*)&Vps[((size_t)key * BSZ + b) * DEXP + h*HDIM + c4*4];
            }
        }
        uint32_t ah[2][4], al[2][4];
        #pragma unroll
        for (int mt = 0; mt < 2; mt++) {
            int r = mt*16 + g;
            int d = vt*128 + ks*16 + 2*t;
            uint2 p0 = *(const uint2*)&Su[r*SPITCH + d];
            uint2 p1 = *(const uint2*)&Su[(r+8)*SPITCH + d];
            uint2 p2 = *(const uint2*)&Su[r*SPITCH + d + 8];
            uint2 p3 = *(const uint2*)&Su[(r+8)*SPITCH + d + 8];
            ah[mt][0] = PERM_HI(p0.x, p0.y); al[mt][0] = PERM_LO(p0.x, p0.y);
            ah[mt][1] = PERM_HI(p1.x, p1.y); al[mt][1] = PERM_LO(p1.x, p1.y);
            ah[mt][2] = PERM_HI(p2.x, p2.y); al[mt][2] = PERM_LO(p2.x, p2.y);
            ah[mt][3] = PERM_HI(p3.x, p3.y); al[mt][3] = PERM_LO(p3.x, p3.y);
        }
        #pragma unroll
        for (int nt = 0; nt < 4; nt++) {
            int nn = nh*32 + nt*8 + g;
            int kk = ks*16 + 2*t;
            uint32_t q0 = buf[kk*VPITCH + nn];
            uint32_t q1 = buf[(kk+1)*VPITCH + nn];
            uint32_t q2 = buf[(kk+8)*VPITCH + nn];
            uint32_t q3 = buf[(kk+9)*VPITCH + nn];
            uint32_t bfh[2] = {PERM_HI(q0, q1), PERM_HI(q2, q3)};
            uint32_t bfl[2] = {PERM_LO(q0, q1), PERM_LO(q2, q3)};
            #pragma unroll
            for (int mt = 0; mt < 2; mt++) {
                mma_bf16(cav[mt][nt], ah[mt], bfh);
                mma_bf16(cav[mt][nt], ah[mt], bfl);
                mma_bf16(cav[mt][nt], al[mt], bfh);
            }
        }
        __syncthreads();
    }

    #pragma unroll
    for (int mt = 0; mt < 2; mt++) {
        int row = mt*16 + g;
        #pragma unroll
        for (int nt = 0; nt < 4; nt++) {
            int col = nh*32 + nt*8 + 2*t;
            *(float2*)&R[(ks*32 + row)*RPITCH + col]     = make_float2(cav[mt][nt][0], cav[mt][nt][1]);
            *(float2*)&R[(ks*32 + row + 8)*RPITCH + col] = make_float2(cav[mt][nt][2], cav[mt][nt][3]);
        }
    }
    __syncthreads();

    {
        int rr = tid >> 4;
        int c  = 2*(tid & 15);
        float2 s  = make_float2(0.f, 0.f);
        float2 s2 = make_float2(0.f, 0.f);
        #pragma unroll
        for (int kq = 0; kq < 8; kq++) {
            float2 p  = *(const float2*)&R[(kq*32 + rr)*RPITCH + c];
            float2 p2 = *(const float2*)&R[(kq*32 + rr)*RPITCH + c + 32];
            s.x += p.x;  s.y += p.y;
            s2.x += p2.x; s2.y += p2.y;
        }
        float inv = rowInv[rr];
        size_t gb = ((size_t)(r0 + rr) * BSZ + b) * DEXP + h*HDIM;
        float2 u  = *(const float2*)&Uc[gb + c];
        *(float2*)&Gout[gb + c] = make_float2(s.x*inv*u.x, s.y*inv*u.y);
        float2 u2 = *(const float2*)&Uc[gb + c + 32];
        *(float2*)&Gout[gb + c + 32] = make_float2(s2.x*inv*u2.x, s2.y*inv*u2.y);
    }
}

// ---------------- depthwise 5x5 conv, row-tiled, packed output ----------------
__global__ __launch_bounds__(256) void dwconv_kernel(
    const float* __restrict__ X, const float* __restrict__ Wc, uint32_t* __restrict__ Yp)
{
    extern __shared__ float sm[];
    float* xs = sm;              // [12*32][33]
    float* ws = sm + 384*33;     // [32][25]
    const int c0 = blockIdx.x * 32;
    const int r0 = blockIdx.y * 8;
    const int b  = blockIdx.z;
    const int tid = threadIdx.x;

    #pragma unroll
    for (int i = 0; i < 48; i++) {
        int idx = tid + 256*i;
        int lp = idx >> 5, c = idx & 31;
        int gr = r0 - 2 + (lp >> 5);
        int j  = lp & 31;
        float v = 0.f;
        if (gr >= 0 && gr < 32)
            v = X[((size_t)(gr*32 + j) * BSZ + b) * DEXP + c0 + c];
        xs[lp*33 + c] = v;
    }
    for (int idx = tid; idx < 32*25; idx += 256) {
        int c = idx / 25, tt = idx % 25;
        ws[c*25 + tt] = Wc[(size_t)(c0 + c) * 25 + tt];
    }
    __syncthreads();

    const int c = tid & 31, pr = tid >> 5;
    for (int s = 0; s < 32; s++) {
        int pos = pr + 8*s;
        int rl = pos >> 5, j = pos & 31;
        float acc = 0.f;
        #pragma unroll
        for (int di = 0; di < 5; di++) {
            int li = rl + di;
            #pragma unroll
            for (int dj = 0; dj < 5; dj++) {
                int jj = j + dj - 2;
                if (jj < 0 || jj >= 32) continue;
                acc += xs[(li*32 + jj)*33 + c] * ws[c*25 + di*5 + dj];
            }
        }
        Yp[((size_t)((r0 + rl)*32 + j) * BSZ + b) * DEXP + c0 + c] = bf16_split_elem(acc);
    }
}

// ---------------- launch ----------------
extern "C" void kernel_launch(void* const* d_in, const int* in_sizes, int n_in,
                              void* d_out, int out_size)
{
    const float* Q   = (const float*)d_in[0];
    const float* V   = (const float*)d_in[2];
    const float* U   = (const float*)d_in[3];
    const float* Wqk = (const float*)d_in[4];
    const float* bqk = (const float*)d_in[5];
    const float* Wv1 = (const float*)d_in[6];
    const float* bv1 = (const float*)d_in[7];
    const float* Wv2 = (const float*)d_in[8];
    const float* bv2 = (const float*)d_in[9];
    const float* Wu1 = (const float*)d_in[10];
    const float* bu1 = (const float*)d_in[11];
    const float* Wu2 = (const float*)d_in[12];
    const float* bu2 = (const float*)d_in[13];
    const float* Wcv = (const float*)d_in[14];
    const float* Wp  = (const float*)d_in[15];
    const float* bp  = (const float*)d_in[16];

    float* out  = (float*)d_out;
    float* attn = (out_size > MROWS*DQK) ? out + (size_t)MROWS*DQK : nullptr;

    uint32_t *Qps, *Vps, *Yp, *Qin, *Vin, *Uin, *pWqk, *pWv1, *pWv2, *pWu1, *pWu2, *pWp;
    float *Uc, *G;
    cudaGetSymbolAddress((void**)&Qps, g_Qps);
    cudaGetSymbolAddress((void**)&Vps, g_Vps);
    cudaGetSymbolAddress((void**)&Uc,  g_Uc);
    cudaGetSymbolAddress((void**)&G,   g_G);
    cudaGetSymbolAddress((void**)&Yp,  g_Yp);
    cudaGetSymbolAddress((void**)&Qin, g_Qin);
    cudaGetSymbolAddress((void**)&Vin, g_Vin);
    cudaGetSymbolAddress((void**)&Uin, g_Uin);
    cudaGetSymbolAddress((void**)&pWqk, g_Wqk);
    cudaGetSymbolAddress((void**)&pWv1, g_Wv1);
    cudaGetSymbolAddress((void**)&pWv2, g_Wv2);
    cudaGetSymbolAddress((void**)&pWu1, g_Wu1);
    cudaGetSymbolAddress((void**)&pWu2, g_Wu2);
    cudaGetSymbolAddress((void**)&pWp, g_Wpp);

    const size_t ATTN_SMEM = (size_t)(32*SPITCH + 128*VPITCH + 32*QPITCH + 32*16 + 32) * 4; // ~174 KB
    const size_t CONV_SMEM = (size_t)(384*33 + 32*25) * sizeof(float);
    cudaFuncSetAttribute(attn_kernel,   cudaFuncAttributeMaxDynamicSharedMemorySize, (int)ATTN_SMEM);
    cudaFuncSetAttribute(dwconv_kernel, cudaFuncAttributeMaxDynamicSharedMemorySize, (int)CONV_SMEM);

    // 0) one fused pack launch for all inputs + weights
    pack_all_kernel<<<2048, 256>>>(Q, V, U, Wqk, Wv1, Wv2, Wu1, Wu2, Wp);

    // 1) Qp = Q @ Wqk + bqk -> packed u32
    {
        dim3 grid(DQK/64, MROWS/64);
        mma_gemm_kernel<<<grid, 256>>>(Qin, pWqk, bqk, Qps, MROWS, DQK, DQK, 1);
    }
    // 2) Vc packed, Uc fp32
    {
        dim3 grid(16, MROWS/64);
        mma_gated_kernel<<<grid, 256>>>(Vin, pWv1, bv1, pWv2, bv2, Vps, 1);
        mma_gated_kernel<<<grid, 256>>>(Uin, pWu1, bu1, pWu2, bu2, Uc, 0);
    }
    // 3) attention
    {
        dim3 grid(LL/AROWS, NHEAD, BSZ);
        attn_kernel<<<grid, 512, ATTN_SMEM>>>(Qps, Vps, Uc, attn, G);
    }
    // 4) depthwise conv -> packed Y
    {
        dim3 grid(16, 4, BSZ);
        dwconv_kernel<<<grid, 256, CONV_SMEM>>>(G, Wcv, Yp);
    }
    // 5) outputs = Y @ Wp + bp
    {
        dim3 grid(DQK/64, MROWS/64);
        mma_gemm_kernel<<<grid, 256>>>(Yp, pWp, bp, out, MROWS, DQK, DEXP, 0);
    }
}

// round 15
// speedup vs baseline: 1.0619x; 1.0088x over previous
#include <cuda_runtime.h>
#include <cuda_bf16.h>
#include <math.h>
#include <stdint.h>

#define LL    1024
#define BSZ   8
#define DQK   256
#define DEXP  512
#define NHEAD 8
#define HDIM  64
#define DATT  32
#define MROWS (LL*BSZ)   // 8192
#define HALF_OUT 256
#define SPITCH 1032
#define KPITCH 40
#define QPITCH 40
#define VPITCH 68
#define RPITCH 72
#define AROWS  32

// ---------------- scratch ----------------
__device__ __align__(256) uint32_t g_Qps[MROWS*DQK];
__device__ __align__(256) uint32_t g_Vps[MROWS*DEXP];
__device__ __align__(256) float    g_Uc [MROWS*DEXP];
__device__ __align__(256) float    g_G  [MROWS*DEXP];
__device__ __align__(256) uint32_t g_Yp [MROWS*DEXP];
__device__ __align__(256) uint32_t g_Qin[MROWS*DQK];
__device__ __align__(256) uint32_t g_Vin[MROWS*DQK];
__device__ __align__(256) uint32_t g_Uin[MROWS*DQK];
__device__ __align__(256) uint32_t g_Wqk[DQK*DQK];
__device__ __align__(256) uint32_t g_Wv1[128*HALF_OUT];
__device__ __align__(256) uint32_t g_Wv2[128*HALF_OUT];
__device__ __align__(256) uint32_t g_Wu1[128*HALF_OUT];
__device__ __align__(256) uint32_t g_Wu2[128*HALF_OUT];
__device__ __align__(256) uint32_t g_Wpp[DEXP*DQK];

// ---------------- helpers ----------------
__device__ __forceinline__ uint32_t bf16_split_elem(float x) {
    __nv_bfloat16 hb = __float2bfloat16_rn(x);
    float hf = __bfloat162float(hb);
    __nv_bfloat16 lb = __float2bfloat16_rn(x - hf);
    return ((uint32_t)__bfloat16_as_ushort(lb) << 16) | (uint32_t)__bfloat16_as_ushort(hb);
}
__device__ __forceinline__ float bf16_unsplit(uint32_t p) {
    return __uint_as_float(p << 16) + __uint_as_float(p & 0xffff0000u);
}

__device__ __forceinline__ void mma_bf16(float* c, const uint32_t* a, const uint32_t* b) {
    asm volatile(
        "mma.sync.aligned.m16n8k16.row.col.f32.bf16.bf16.f32 "
        "{%0,%1,%2,%3},{%4,%5,%6,%7},{%8,%9},{%0,%1,%2,%3};"
        : "+f"(c[0]), "+f"(c[1]), "+f"(c[2]), "+f"(c[3])
        : "r"(a[0]), "r"(a[1]), "r"(a[2]), "r"(a[3]), "r"(b[0]), "r"(b[1]));
}

#define PERM_HI(p0, p1) __byte_perm((p0), (p1), 0x5410)
#define PERM_LO(p0, p1) __byte_perm((p0), (p1), 0x7632)

// ---------------- fused pack ----------------
#define SZ_IN   (MROWS*DQK)
#define SZ_WQK  (DQK*DQK)
#define SZ_WH   (128*HALF_OUT)
#define SZ_WP   (DEXP*DQK)
#define PACK_TOTAL (3*SZ_IN + SZ_WQK + 4*SZ_WH + SZ_WP)
#define PACK_V4    (PACK_TOTAL/4)

__device__ __forceinline__ void pack4(const float* __restrict__ s, uint32_t* __restrict__ d, int e) {
    float4 x = *(const float4*)&s[e];
    uint4 y;
    y.x = bf16_split_elem(x.x); y.y = bf16_split_elem(x.y);
    y.z = bf16_split_elem(x.z); y.w = bf16_split_elem(x.w);
    *(uint4*)&d[e] = y;
}

__global__ __launch_bounds__(256) void pack_all_kernel(
    const float* __restrict__ Q, const float* __restrict__ V, const float* __restrict__ U,
    const float* __restrict__ Wqk,
    const float* __restrict__ Wv1, const float* __restrict__ Wv2,
    const float* __restrict__ Wu1, const float* __restrict__ Wu2,
    const float* __restrict__ Wp)
{
    for (int v = blockIdx.x * 256 + threadIdx.x; v < PACK_V4; v += gridDim.x * 256) {
        int e = v * 4;
        if (e < SZ_IN)  { pack4(Q,   g_Qin, e); continue; }
        e -= SZ_IN;
        if (e < SZ_IN)  { pack4(V,   g_Vin, e); continue; }
        e -= SZ_IN;
        if (e < SZ_IN)  { pack4(U,   g_Uin, e); continue; }
        e -= SZ_IN;
        if (e < SZ_WQK) { pack4(Wqk, g_Wqk, e); continue; }
        e -= SZ_WQK;
        if (e < SZ_WH)  { pack4(Wv1, g_Wv1, e); continue; }
        e -= SZ_WH;
        if (e < SZ_WH)  { pack4(Wv2, g_Wv2, e); continue; }
        e -= SZ_WH;
        if (e < SZ_WH)  { pack4(Wu1, g_Wu1, e); continue; }
        e -= SZ_WH;
        if (e < SZ_WH)  { pack4(Wu2, g_Wu2, e); continue; }
        e -= SZ_WH;
        pack4(Wp, g_Wpp, e);
    }
}

// ---------------- tensor-core GEMM + bias, PACKED operands ----------------
__global__ __launch_bounds__(256) void mma_gemm_kernel(
    const uint32_t* __restrict__ A, const uint32_t* __restrict__ B,
    const float* __restrict__ bias, void* __restrict__ Cv,
    int M, int N, int K, int mode)
{
    __shared__ uint32_t As[64*40];
    __shared__ uint32_t Bs[32*68];
    const int m0 = blockIdx.y * 64, n0 = blockIdx.x * 64;
    const int tid = threadIdx.x, lane = tid & 31, w = tid >> 5;
    const int g = lane >> 2, t = lane & 3;
    const int mw = w >> 2, nq = w & 3;

    uint32_t aReg[8], bReg[8];
    #pragma unroll
    for (int i = 0; i < 8; i++) {
        int idx = 256*i + tid;
        aReg[i] = A[(size_t)(m0 + (idx >> 5)) * K + (idx & 31)];
        bReg[i] = B[(size_t)(idx >> 6) * N + n0 + (idx & 63)];
    }
    float acc[2][2][4] = {};

    for (int k0 = 0; k0 < K; k0 += 32) {
        #pragma unroll
        for (int i = 0; i < 8; i++) {
            int idx = 256*i + tid;
            As[(idx >> 5)*40 + (idx & 31)] = aReg[i];
            Bs[(idx >> 6)*68 + (idx & 63)] = bReg[i];
        }
        __syncthreads();
        if (k0 + 32 < K) {
            #pragma unroll
            for (int i = 0; i < 8; i++) {
                int idx = 256*i + tid;
                aReg[i] = A[(size_t)(m0 + (idx >> 5)) * K + k0 + 32 + (idx & 31)];
                bReg[i] = B[(size_t)(k0 + 32 + (idx >> 6)) * N + n0 + (idx & 63)];
            }
        }
        #pragma unroll
        for (int ks = 0; ks < 2; ks++) {
            uint32_t ah[2][4], al[2][4];
            #pragma unroll
            for (int mt = 0; mt < 2; mt++) {
                int r = mw*32 + mt*16 + g;
                int d = ks*16 + 2*t;
                uint2 p0 = *(const uint2*)&As[r*40 + d];
                uint2 p1 = *(const uint2*)&As[(r+8)*40 + d];
                uint2 p2 = *(const uint2*)&As[r*40 + d + 8];
                uint2 p3 = *(const uint2*)&As[(r+8)*40 + d + 8];
                ah[mt][0] = PERM_HI(p0.x, p0.y); al[mt][0] = PERM_LO(p0.x, p0.y);
                ah[mt][1] = PERM_HI(p1.x, p1.y); al[mt][1] = PERM_LO(p1.x, p1.y);
                ah[mt][2] = PERM_HI(p2.x, p2.y); al[mt][2] = PERM_LO(p2.x, p2.y);
                ah[mt][3] = PERM_HI(p3.x, p3.y); al[mt][3] = PERM_LO(p3.x, p3.y);
            }
            #pragma unroll
            for (int nt = 0; nt < 2; nt++) {
                int nn = nq*16 + nt*8 + g;
                int kk = ks*16 + 2*t;
                uint32_t q0 = Bs[kk*68 + nn];
                uint32_t q1 = Bs[(kk+1)*68 + nn];
                uint32_t q2 = Bs[(kk+8)*68 + nn];
                uint32_t q3 = Bs[(kk+9)*68 + nn];
                uint32_t bfh[2] = {PERM_HI(q0, q1), PERM_HI(q2, q3)};
                uint32_t bfl[2] = {PERM_LO(q0, q1), PERM_LO(q2, q3)};
                #pragma unroll
                for (int mt = 0; mt < 2; mt++) {
                    mma_bf16(acc[mt][nt], ah[mt], bfh);
                    mma_bf16(acc[mt][nt], ah[mt], bfl);
                    mma_bf16(acc[mt][nt], al[mt], bfh);
                }
            }
        }
        __syncthreads();
    }

    #pragma unroll
    for (int mt = 0; mt < 2; mt++) {
        int row = m0 + mw*32 + mt*16 + g;
        #pragma unroll
        for (int nt = 0; nt < 2; nt++) {
            int col = n0 + nq*16 + nt*8 + 2*t;
            float b0 = bias[col], b1 = bias[col+1];
            float v0 = acc[mt][nt][0] + b0, v1 = acc[mt][nt][1] + b1;
            float v2 = acc[mt][nt][2] + b0, v3 = acc[mt][nt][3] + b1;
            if (mode == 0) {
                float* C = (float*)Cv;
                C[(size_t)row*N + col]       = v0;
                C[(size_t)row*N + col + 1]   = v1;
                C[(size_t)(row+8)*N + col]     = v2;
                C[(size_t)(row+8)*N + col + 1] = v3;
            } else {
                uint32_t* C = (uint32_t*)Cv;
                C[(size_t)row*N + col]       = bf16_split_elem(v0);
                C[(size_t)row*N + col + 1]   = bf16_split_elem(v1);
                C[(size_t)(row+8)*N + col]     = bf16_split_elem(v2);
                C[(size_t)(row+8)*N + col + 1] = bf16_split_elem(v3);
            }
        }
    }
}

// ---------------- fused gated half-projections (V and U in one launch via blockIdx.z) ----------------
__global__ __launch_bounds__(256) void mma_gated_kernel(
    const uint32_t* __restrict__ Xv, const uint32_t* __restrict__ Xu,
    const uint32_t* __restrict__ Wv1p, const float* __restrict__ bv1,
    const uint32_t* __restrict__ Wv2p, const float* __restrict__ bv2,
    const uint32_t* __restrict__ Wu1p, const float* __restrict__ bu1,
    const uint32_t* __restrict__ Wu2p, const float* __restrict__ bu2,
    uint32_t* __restrict__ Yvp, float* __restrict__ Yuf)
{
    __shared__ uint32_t As[64*40];
    __shared__ uint32_t Bs[32*36];
    const int which = blockIdx.z;                 // 0 = V (packed out), 1 = U (fp32 out)
    const uint32_t* X  = which ? Xu : Xv;
    const int c0   = blockIdx.x * 32;
    const int head = c0 >> 6;
    const int is2  = (c0 >> 5) & 1;
    const uint32_t* W  = which ? (is2 ? Wu2p : Wu1p) : (is2 ? Wv2p : Wv1p);
    const float*    bb = which ? (is2 ? bu2 : bu1)  : (is2 ? bv2 : bv1);
    const int wc0 = head * 32;
    const uint32_t* Ain = X + (is2 ? 128 : 0);
    const int m0 = blockIdx.y * 64;
    const int tid = threadIdx.x, lane = tid & 31, w = tid >> 5;
    const int g = lane >> 2, t = lane & 3;
    const int mw = w >> 2, nq = w & 3;

    uint32_t aReg[8], bReg[4];
    #pragma unroll
    for (int i = 0; i < 8; i++) {
        int idx = 256*i + tid;
        aReg[i] = Ain[(size_t)(m0 + (idx >> 5)) * 256 + (idx & 31)];
    }
    #pragma unroll
    for (int i = 0; i < 4; i++) {
        int idx = 256*i + tid;
        bReg[i] = W[(size_t)(idx >> 5) * HALF_OUT + wc0 + (idx & 31)];
    }
    float acc[2][4] = {};

    for (int k0 = 0; k0 < 128; k0 += 32) {
        #pragma unroll
        for (int i = 0; i < 8; i++) {
            int idx = 256*i + tid;
            As[(idx >> 5)*40 + (idx & 31)] = aReg[i];
        }
        #pragma unroll
        for (int i = 0; i < 4; i++) {
            int idx = 256*i + tid;
            Bs[(idx >> 5)*36 + (idx & 31)] = bReg[i];
        }
        __syncthreads();
        if (k0 + 32 < 128) {
            #pragma unroll
            for (int i = 0; i < 8; i++) {
                int idx = 256*i + tid;
                aReg[i] = Ain[(size_t)(m0 + (idx >> 5)) * 256 + k0 + 32 + (idx & 31)];
            }
            #pragma unroll
            for (int i = 0; i < 4; i++) {
                int idx = 256*i + tid;
                bReg[i] = W[(size_t)(k0 + 32 + (idx >> 5)) * HALF_OUT + wc0 + (idx & 31)];
            }
        }
        #pragma unroll
        for (int ks = 0; ks < 2; ks++) {
            uint32_t ah[2][4], al[2][4];
            #pragma unroll
            for (int mt = 0; mt < 2; mt++) {
                int r = mw*32 + mt*16 + g;
                int d = ks*16 + 2*t;
                uint2 p0 = *(const uint2*)&As[r*40 + d];
                uint2 p1 = *(const uint2*)&As[(r+8)*40 + d];
                uint2 p2 = *(const uint2*)&As[r*40 + d + 8];
                uint2 p3 = *(const uint2*)&As[(r+8)*40 + d + 8];
                ah[mt][0] = PERM_HI(p0.x, p0.y); al[mt][0] = PERM_LO(p0.x, p0.y);
                ah[mt][1] = PERM_HI(p1.x, p1.y); al[mt][1] = PERM_LO(p1.x, p1.y);
                ah[mt][2] = PERM_HI(p2.x, p2.y); al[mt][2] = PERM_LO(p2.x, p2.y);
                ah[mt][3] = PERM_HI(p3.x, p3.y); al[mt][3] = PERM_LO(p3.x, p3.y);
            }
            {
                int nn = nq*8 + g;
                int kk = ks*16 + 2*t;
                uint32_t q0 = Bs[kk*36 + nn];
                uint32_t q1 = Bs[(kk+1)*36 + nn];
                uint32_t q2 = Bs[(kk+8)*36 + nn];
                uint32_t q3 = Bs[(kk+9)*36 + nn];
                uint32_t bfh[2] = {PERM_HI(q0, q1), PERM_HI(q2, q3)};
                uint32_t bfl[2] = {PERM_LO(q0, q1), PERM_LO(q2, q3)};
                #pragma unroll
                for (int mt = 0; mt < 2; mt++) {
                    mma_bf16(acc[mt], ah[mt], bfh);
                    mma_bf16(acc[mt], ah[mt], bfl);
                    mma_bf16(acc[mt], al[mt], bfh);
                }
            }
        }
        __syncthreads();
    }

    #pragma unroll
    for (int mt = 0; mt < 2; mt++) {
        int row = m0 + mw*32 + mt*16 + g;
        int col = nq*8 + 2*t;
        float b0 = bb[wc0 + col], b1 = bb[wc0 + col + 1];
        float v[4] = {acc[mt][0] + b0, acc[mt][1] + b1, acc[mt][2] + b0, acc[mt][3] + b1};
        #pragma unroll
        for (int j = 0; j < 4; j++) v[j] = v[j] / (1.0f + __expf(-v[j]));
        if (!which) {
            Yvp[(size_t)row*DEXP + c0 + col]       = bf16_split_elem(v[0]);
            Yvp[(size_t)row*DEXP + c0 + col + 1]   = bf16_split_elem(v[1]);
            Yvp[(size_t)(row+8)*DEXP + c0 + col]     = bf16_split_elem(v[2]);
            Yvp[(size_t)(row+8)*DEXP + c0 + col + 1] = bf16_split_elem(v[3]);
        } else {
            Yuf[(size_t)row*DEXP + c0 + col]       = v[0];
            Yuf[(size_t)row*DEXP + c0 + col + 1]   = v[1];
            Yuf[(size_t)(row+8)*DEXP + c0 + col]     = v[2];
            Yuf[(size_t)(row+8)*DEXP + c0 + col + 1] = v[3];
        }
    }
}

// ---------------- fused attention (R10/R13 winner + exp2 fold + float4 attn writes) ----------------
__global__ __launch_bounds__(512, 1) void attn_kernel(
    const uint32_t* __restrict__ Qps, const uint32_t* __restrict__ Vps,
    const float* __restrict__ Uc, float* __restrict__ attn_out,
    float* __restrict__ Gout)
{
    extern __shared__ float sm[];
    float*    Sf   = sm;
    uint32_t* Su   = (uint32_t*)sm;
    uint32_t* buf  = (uint32_t*)(sm + 32*SPITCH);
    uint32_t* Qb   = buf + 128*VPITCH;
    float*    wm   = (float*)(Qb + 32*QPITCH);
    float*    rowInv = wm + 32*16;
    float*    R    = sm;

    const int r0 = blockIdx.x * AROWS;
    const int h  = blockIdx.y, b = blockIdx.z;
    const int tid  = threadIdx.x;
    const int lane = tid & 31;
    const int w    = tid >> 5;
    const int g    = lane >> 2;
    const int t    = lane & 3;
    // scale * log2(e): softmax computed in base 2
    const float scale = 0.17677669529663687f * 1.4426950408889634f;

    #pragma unroll
    for (int i = 0; i < 2; i++) {
        int idx = 512*i + tid;
        int r = idx >> 5, d = idx & 31;
        Qb[r*QPITCH + d] = Qps[((size_t)(r0 + r) * BSZ + b) * DQK + h*DATT + d];
    }
    uint32_t kreg[8];
    #pragma unroll
    for (int i = 0; i < 8; i++) {
        int idx = 512*i + tid;
        int key = idx >> 5, d = idx & 31;
        kreg[i] = Qps[((size_t)key * BSZ + b) * DQK + h*DATT + d];
    }
    __syncthreads();

    uint32_t qa_hi[2][2][4], qa_lo[2][2][4];
    #pragma unroll
    for (int mt = 0; mt < 2; mt++) {
        int r = mt*16 + g;
        #pragma unroll
        for (int ks = 0; ks < 2; ks++) {
            int d = ks*16 + 2*t;
            uint2 p0 = *(const uint2*)&Qb[r*QPITCH + d];
            uint2 p1 = *(const uint2*)&Qb[(r+8)*QPITCH + d];
            uint2 p2 = *(const uint2*)&Qb[r*QPITCH + d + 8];
            uint2 p3 = *(const uint2*)&Qb[(r+8)*QPITCH + d + 8];
            qa_hi[mt][ks][0] = PERM_HI(p0.x, p0.y); qa_lo[mt][ks][0] = PERM_LO(p0.x, p0.y);
            qa_hi[mt][ks][1] = PERM_HI(p1.x, p1.y); qa_lo[mt][ks][1] = PERM_LO(p1.x, p1.y);
            qa_hi[mt][ks][2] = PERM_HI(p2.x, p2.y); qa_lo[mt][ks][2] = PERM_LO(p2.x, p2.y);
            qa_hi[mt][ks][3] = PERM_HI(p3.x, p3.y); qa_lo[mt][ks][3] = PERM_LO(p3.x, p3.y);
        }
    }

    float mx[2][2] = {{-1e30f,-1e30f},{-1e30f,-1e30f}};
    for (int kt = 0; kt < 8; kt++) {
        #pragma unroll
        for (int i = 0; i < 8; i++) {
            int idx = 512*i + tid;
            buf[(idx >> 5)*KPITCH + (idx & 31)] = kreg[i];
        }
        __syncthreads();
        if (kt < 7) {
            int base = (kt + 1) * 128;
            #pragma unroll
            for (int i = 0; i < 8; i++) {
                int idx = 512*i + tid;
                int key = base + (idx >> 5), d = idx & 31;
                kreg[i] = Qps[((size_t)key * BSZ + b) * DQK + h*DATT + d];
            }
        }
        uint32_t bh[2][2], bl[2][2];
        {
            int key = w*8 + g;
            #pragma unroll
            for (int ks = 0; ks < 2; ks++) {
                int d = ks*16 + 2*t;
                uint2 p0 = *(const uint2*)&buf[key*KPITCH + d];
                uint2 p1 = *(const uint2*)&buf[key*KPITCH + d + 8];
                bh[ks][0] = PERM_HI(p0.x, p0.y); bl[ks][0] = PERM_LO(p0.x, p0.y);
                bh[ks][1] = PERM_HI(p1.x, p1.y); bl[ks][1] = PERM_LO(p1.x, p1.y);
            }
        }
        __syncthreads();
        #pragma unroll
        for (int mt = 0; mt < 2; mt++) {
            float c[4] = {0.f, 0.f, 0.f, 0.f};
            #pragma unroll
            for (int ks = 0; ks < 2; ks++) {
                mma_bf16(c, qa_hi[mt][ks], bh[ks]);
                mma_bf16(c, qa_hi[mt][ks], bl[ks]);
                mma_bf16(c, qa_lo[mt][ks], bh[ks]);
            }
            c[0] *= scale; c[1] *= scale; c[2] *= scale; c[3] *= scale;
            mx[mt][0] = fmaxf(mx[mt][0], fmaxf(c[0], c[1]));
            mx[mt][1] = fmaxf(mx[mt][1], fmaxf(c[2], c[3]));
            int row = mt*16 + g;
            int col = kt*128 + w*8 + 2*t;
            *(float2*)&Sf[row*SPITCH + col]     = make_float2(c[0], c[1]);
            *(float2*)&Sf[(row+8)*SPITCH + col] = make_float2(c[2], c[3]);
        }
    }
    #pragma unroll
    for (int mt = 0; mt < 2; mt++) {
        #pragma unroll
        for (int j = 0; j < 2; j++) {
            mx[mt][j] = fmaxf(mx[mt][j], __shfl_xor_sync(0xffffffffu, mx[mt][j], 1));
            mx[mt][j] = fmaxf(mx[mt][j], __shfl_xor_sync(0xffffffffu, mx[mt][j], 2));
        }
        if (t == 0) {
            wm[(mt*16 + g)*16 + w]     = mx[mt][0];
            wm[(mt*16 + 8 + g)*16 + w] = mx[mt][1];
        }
    }
    __syncthreads();

    uint4 vreg[4];
    #pragma unroll
    for (int i = 0; i < 4; i++) {
        int f = 512*i + tid;
        int key = f >> 4, c4 = f & 15;
        vreg[i] = *(const uint4*)&Vps[((size_t)key * BSZ + b) * DEXP + h*HDIM + c4*4];
    }

    #pragma unroll
    for (int rr = 0; rr < 2; rr++) {
        int r = w + 16*rr;
        float* row = Sf + r*SPITCH;
        uint32_t* urow = Su + r*SPITCH;
        float m = wm[r*16 + (lane & 15)];
        #pragma unroll
        for (int o = 8; o; o >>= 1) m = fmaxf(m, __shfl_xor_sync(0xffffffffu, m, o));
        float s = 0.f;
        #pragma unroll 4
        for (int i = 0; i < 16; i++) {
            int k = 2*lane + 64*i;
            float2 x = *(const float2*)&row[k];
            float e0 = exp2f(x.x - m), e1 = exp2f(x.y - m);
            s += e0 + e1;
            uint2 pk = make_uint2(bf16_split_elem(e0), bf16_split_elem(e1));
            *(uint2*)&urow[k] = pk;
        }
        #pragma unroll
        for (int o = 16; o; o >>= 1) s += __shfl_xor_sync(0xffffffffu, s, o);
        float inv = 1.0f / s;
        if (lane == 0) rowInv[r] = inv;
        __syncwarp();
        float* gp = attn_out ? attn_out + (((size_t)(b*NHEAD + h) * LL + (r0 + r)) * LL) : nullptr;
        if (gp) {
            #pragma unroll 2
            for (int i = 0; i < 8; i++) {
                int k = 4*lane + 128*i;
                uint4 p = *(const uint4*)&urow[k];
                *(float4*)&gp[k] = make_float4(bf16_unsplit(p.x) * inv, bf16_unsplit(p.y) * inv,
                                               bf16_unsplit(p.z) * inv, bf16_unsplit(p.w) * inv);
            }
        }
    }
    __syncthreads();

    const int ks = w >> 1;
    const int nh = w & 1;
    float cav[2][4][4] = {};
    for (int vt = 0; vt < 8; vt++) {
        #pragma unroll
        for (int i = 0; i < 4; i++) {
            int f = 512*i + tid;
            int key = f >> 4, c4 = f & 15;
            *(uint4*)&buf[key*VPITCH + c4*4] = vreg[i];
        }
        __syncthreads();
        if (vt < 7) {
            int base = (vt + 1) * 128;
            #pragma unroll
            for (int i = 0; i < 4; i++) {
                int f = 512*i + tid;
                int key = base + (f >> 4), c4 = f & 15;
                vreg[i] = *(const uint4*)&Vps[((size_t)key * BSZ + b) * DEXP + h*HDIM + c4*4];
            }
        }
        uint32_t ah[2][4], al[2][4];
        #pragma unroll
        for (int mt = 0; mt < 2; mt++) {
            int r = mt*16 + g;
            int d = vt*128 + ks*16 + 2*t;
            uint2 p0 = *(const uint2*)&Su[r*SPITCH + d];
            uint2 p1 = *(const uint2*)&Su[(r+8)*SPITCH + d];
            uint2 p2 = *(const uint2*)&Su[r*SPITCH + d + 8];
            uint2 p3 = *(const uint2*)&Su[(r+8)*SPITCH + d + 8];
            ah[mt][0] = PERM_HI(p0.x, p0.y); al[mt][0] = PERM_LO(p0.x, p0.y);
            ah[mt][1] = PERM_HI(p1.x, p1.y); al[mt][1] = PERM_LO(p1.x, p1.y);
            ah[mt][2] = PERM_HI(p2.x, p2.y); al[mt][2] = PERM_LO(p2.x, p2.y);
            ah[mt][3] = PERM_HI(p3.x, p3.y); al[mt][3] = PERM_LO(p3.x, p3.y);
        }
        #pragma unroll
        for (int nt = 0; nt < 4; nt++) {
            int nn = nh*32 + nt*8 + g;
            int kk = ks*16 + 2*t;
            uint32_t q0 = buf[kk*VPITCH + nn];
            uint32_t q1 = buf[(kk+1)*VPITCH + nn];
            uint32_t q2 = buf[(kk+8)*VPITCH + nn];
            uint32_t q3 = buf[(kk+9)*VPITCH + nn];
            uint32_t bfh[2] = {PERM_HI(q0, q1), PERM_HI(q2, q3)};
            uint32_t bfl[2] = {PERM_LO(q0, q1), PERM_LO(q2, q3)};
            #pragma unroll
            for (int mt = 0; mt < 2; mt++) {
                mma_bf16(cav[mt][nt], ah[mt], bfh);
                mma_bf16(cav[mt][nt], ah[mt], bfl);
                mma_bf16(cav[mt][nt], al[mt], bfh);
            }
        }
        __syncthreads();
    }

    #pragma unroll
    for (int mt = 0; mt < 2; mt++) {
        int row = mt*16 + g;
        #pragma unroll
        for (int nt = 0; nt < 4; nt++) {
            int col = nh*32 + nt*8 + 2*t;
            *(float2*)&R[(ks*32 + row)*RPITCH + col]     = make_float2(cav[mt][nt][0], cav[mt][nt][1]);
            *(float2*)&R[(ks*32 + row + 8)*RPITCH + col] = make_float2(cav[mt][nt][2], cav[mt][nt][3]);
        }
    }
    __syncthreads();

    {
        int rr = tid >> 4;
        int c  = 2*(tid & 15);
        float2 s  = make_float2(0.f, 0.f);
        float2 s2 = make_float2(0.f, 0.f);
        #pragma unroll
        for (int kq = 0; kq < 8; kq++) {
            float2 p  = *(const float2*)&R[(kq*32 + rr)*RPITCH + c];
            float2 p2 = *(const float2*)&R[(kq*32 + rr)*RPITCH + c + 32];
            s.x += p.x;  s.y += p.y;
            s2.x += p2.x; s2.y += p2.y;
        }
        float inv = rowInv[rr];
        size_t gb = ((size_t)(r0 + rr) * BSZ + b) * DEXP + h*HDIM;
        float2 u  = *(const float2*)&Uc[gb + c];
        *(float2*)&Gout[gb + c] = make_float2(s.x*inv*u.x, s.y*inv*u.y);
        float2 u2 = *(const float2*)&Uc[gb + c + 32];
        *(float2*)&Gout[gb + c + 32] = make_float2(s2.x*inv*u2.x, s2.y*inv*u2.y);
    }
}

// ---------------- depthwise 5x5 conv, row-tiled, packed output ----------------
__global__ __launch_bounds__(256) void dwconv_kernel(
    const float* __restrict__ X, const float* __restrict__ Wc, uint32_t* __restrict__ Yp)
{
    extern __shared__ float sm[];
    float* xs = sm;              // [12*32][33]
    float* ws = sm + 384*33;     // [32][25]
    const int c0 = blockIdx.x * 32;
    const int r0 = blockIdx.y * 8;
    const int b  = blockIdx.z;
    const int tid = threadIdx.x;

    #pragma unroll
    for (int i = 0; i < 48; i++) {
        int idx = tid + 256*i;
        int lp = idx >> 5, c = idx & 31;
        int gr = r0 - 2 + (lp >> 5);
        int j  = lp & 31;
        float v = 0.f;
        if (gr >= 0 && gr < 32)
            v = X[((size_t)(gr*32 + j) * BSZ + b) * DEXP + c0 + c];
        xs[lp*33 + c] = v;
    }
    for (int idx = tid; idx < 32*25; idx += 256) {
        int c = idx / 25, tt = idx % 25;
        ws[c*25 + tt] = Wc[(size_t)(c0 + c) * 25 + tt];
    }
    __syncthreads();

    const int c = tid & 31, pr = tid >> 5;
    for (int s = 0; s < 32; s++) {
        int pos = pr + 8*s;
        int rl = pos >> 5, j = pos & 31;
        float acc = 0.f;
        #pragma unroll
        for (int di = 0; di < 5; di++) {
            int li = rl + di;
            #pragma unroll
            for (int dj = 0; dj < 5; dj++) {
                int jj = j + dj - 2;
                if (jj < 0 || jj >= 32) continue;
                acc += xs[(li*32 + jj)*33 + c] * ws[c*25 + di*5 + dj];
            }
        }
        Yp[((size_t)((r0 + rl)*32 + j) * BSZ + b) * DEXP + c0 + c] = bf16_split_elem(acc);
    }
}

// ---------------- launch ----------------
extern "C" void kernel_launch(void* const* d_in, const int* in_sizes, int n_in,
                              void* d_out, int out_size)
{
    const float* Q   = (const float*)d_in[0];
    const float* V   = (const float*)d_in[2];
    const float* U   = (const float*)d_in[3];
    const float* Wqk = (const float*)d_in[4];
    const float* bqk = (const float*)d_in[5];
    const float* Wv1 = (const float*)d_in[6];
    const float* bv1 = (const float*)d_in[7];
    const float* Wv2 = (const float*)d_in[8];
    const float* bv2 = (const float*)d_in[9];
    const float* Wu1 = (const float*)d_in[10];
    const float* bu1 = (const float*)d_in[11];
    const float* Wu2 = (const float*)d_in[12];
    const float* bu2 = (const float*)d_in[13];
    const float* Wcv = (const float*)d_in[14];
    const float* Wp  = (const float*)d_in[15];
    const float* bp  = (const float*)d_in[16];

    float* out  = (float*)d_out;
    float* attn = (out_size > MROWS*DQK) ? out + (size_t)MROWS*DQK : nullptr;

    uint32_t *Qps, *Vps, *Yp, *Qin, *Vin, *Uin, *pWqk, *pWv1, *pWv2, *pWu1, *pWu2, *pWp;
    float *Uc, *G;
    cudaGetSymbolAddress((void**)&Qps, g_Qps);
    cudaGetSymbolAddress((void**)&Vps, g_Vps);
    cudaGetSymbolAddress((void**)&Uc,  g_Uc);
    cudaGetSymbolAddress((void**)&G,   g_G);
    cudaGetSymbolAddress((void**)&Yp,  g_Yp);
    cudaGetSymbolAddress((void**)&Qin, g_Qin);
    cudaGetSymbolAddress((void**)&Vin, g_Vin);
    cudaGetSymbolAddress((void**)&Uin, g_Uin);
    cudaGetSymbolAddress((void**)&pWqk, g_Wqk);
    cudaGetSymbolAddress((void**)&pWv1, g_Wv1);
    cudaGetSymbolAddress((void**)&pWv2, g_Wv2);
    cudaGetSymbolAddress((void**)&pWu1, g_Wu1);
    cudaGetSymbolAddress((void**)&pWu2, g_Wu2);
    cudaGetSymbolAddress((void**)&pWp, g_Wpp);

    const size_t ATTN_SMEM = (size_t)(32*SPITCH + 128*VPITCH + 32*QPITCH + 32*16 + 32) * 4; // ~174 KB
    const size_t CONV_SMEM = (size_t)(384*33 + 32*25) * sizeof(float);
    cudaFuncSetAttribute(attn_kernel,   cudaFuncAttributeMaxDynamicSharedMemorySize, (int)ATTN_SMEM);
    cudaFuncSetAttribute(dwconv_kernel, cudaFuncAttributeMaxDynamicSharedMemorySize, (int)CONV_SMEM);

    // 0) one fused pack launch for all inputs + weights
    pack_all_kernel<<<2048, 256>>>(Q, V, U, Wqk, Wv1, Wv2, Wu1, Wu2, Wp);

    // 1) Qp = Q @ Wqk + bqk -> packed u32
    {
        dim3 grid(DQK/64, MROWS/64);
        mma_gemm_kernel<<<grid, 256>>>(Qin, pWqk, bqk, Qps, MROWS, DQK, DQK, 1);
    }
    // 2) Vc packed + Uc fp32 in ONE launch
    {
        dim3 grid(16, MROWS/64, 2);
        mma_gated_kernel<<<grid, 256>>>(Vin, Uin, pWv1, bv1, pWv2, bv2,
                                        pWu1, bu1, pWu2, bu2, Vps, Uc);
    }
    // 3) attention
    {
        dim3 grid(LL/AROWS, NHEAD, BSZ);
        attn_kernel<<<grid, 512, ATTN_SMEM>>>(Qps, Vps, Uc, attn, G);
    }
    // 4) depthwise conv -> packed Y
    {
        dim3 grid(16, 4, BSZ);
        dwconv_kernel<<<grid, 256, CONV_SMEM>>>(G, Wcv, Yp);
    }
    // 5) outputs = Y @ Wp + bp
    {
        dim3 grid(DQK/64, MROWS/64);
        mma_gemm_kernel<<<grid, 256>>>(Yp, pWp, bp, out, MROWS, DQK, DEXP, 0);
    }
}

// round 16
// speedup vs baseline: 1.0828x; 1.0196x over previous
#include <cuda_runtime.h>
#include <cuda_bf16.h>
#include <math.h>
#include <stdint.h>

#define LL    1024
#define BSZ   8
#define DQK   256
#define DEXP  512
#define NHEAD 8
#define HDIM  64
#define DATT  32
#define MROWS (LL*BSZ)   // 8192
#define HALF_OUT 256
#define SPITCH 1032
#define QPITCH 40
#define RPITCH 72
#define AROWS  32

// ---------------- scratch ----------------
__device__ __align__(256) uint32_t g_Qps[MROWS*DQK];
__device__ __align__(256) uint32_t g_Vps[MROWS*DEXP];
__device__ __align__(256) float    g_Uc [MROWS*DEXP];
__device__ __align__(256) float    g_G  [MROWS*DEXP];
__device__ __align__(256) uint32_t g_Yp [MROWS*DEXP];
__device__ __align__(256) uint32_t g_Qin[MROWS*DQK];
__device__ __align__(256) uint32_t g_Vin[MROWS*DQK];
__device__ __align__(256) uint32_t g_Uin[MROWS*DQK];
__device__ __align__(256) uint32_t g_Wqk[DQK*DQK];
__device__ __align__(256) uint32_t g_Wv1[128*HALF_OUT];
__device__ __align__(256) uint32_t g_Wv2[128*HALF_OUT];
__device__ __align__(256) uint32_t g_Wu1[128*HALF_OUT];
__device__ __align__(256) uint32_t g_Wu2[128*HALF_OUT];
__device__ __align__(256) uint32_t g_Wpp[DEXP*DQK];

// ---------------- helpers ----------------
__device__ __forceinline__ uint32_t bf16_split_elem(float x) {
    __nv_bfloat16 hb = __float2bfloat16_rn(x);
    float hf = __bfloat162float(hb);
    __nv_bfloat16 lb = __float2bfloat16_rn(x - hf);
    return ((uint32_t)__bfloat16_as_ushort(lb) << 16) | (uint32_t)__bfloat16_as_ushort(hb);
}
__device__ __forceinline__ float bf16_unsplit(uint32_t p) {
    return __uint_as_float(p << 16) + __uint_as_float(p & 0xffff0000u);
}

__device__ __forceinline__ void mma_bf16(float* c, const uint32_t* a, const uint32_t* b) {
    asm volatile(
        "mma.sync.aligned.m16n8k16.row.col.f32.bf16.bf16.f32 "
        "{%0,%1,%2,%3},{%4,%5,%6,%7},{%8,%9},{%0,%1,%2,%3};"
        : "+f"(c[0]), "+f"(c[1]), "+f"(c[2]), "+f"(c[3])
        : "r"(a[0]), "r"(a[1]), "r"(a[2]), "r"(a[3]), "r"(b[0]), "r"(b[1]));
}

#define PERM_HI(p0, p1) __byte_perm((p0), (p1), 0x5410)
#define PERM_LO(p0, p1) __byte_perm((p0), (p1), 0x7632)

// ---------------- fused pack ----------------
#define SZ_IN   (MROWS*DQK)
#define SZ_WQK  (DQK*DQK)
#define SZ_WH   (128*HALF_OUT)
#define SZ_WP   (DEXP*DQK)
#define PACK_TOTAL (3*SZ_IN + SZ_WQK + 4*SZ_WH + SZ_WP)
#define PACK_V4    (PACK_TOTAL/4)

__device__ __forceinline__ void pack4(const float* __restrict__ s, uint32_t* __restrict__ d, int e) {
    float4 x = *(const float4*)&s[e];
    uint4 y;
    y.x = bf16_split_elem(x.x); y.y = bf16_split_elem(x.y);
    y.z = bf16_split_elem(x.z); y.w = bf16_split_elem(x.w);
    *(uint4*)&d[e] = y;
}

__global__ __launch_bounds__(256) void pack_all_kernel(
    const float* __restrict__ Q, const float* __restrict__ V, const float* __restrict__ U,
    const float* __restrict__ Wqk,
    const float* __restrict__ Wv1, const float* __restrict__ Wv2,
    const float* __restrict__ Wu1, const float* __restrict__ Wu2,
    const float* __restrict__ Wp)
{
    for (int v = blockIdx.x * 256 + threadIdx.x; v < PACK_V4; v += gridDim.x * 256) {
        int e = v * 4;
        if (e < SZ_IN)  { pack4(Q,   g_Qin, e); continue; }
        e -= SZ_IN;
        if (e < SZ_IN)  { pack4(V,   g_Vin, e); continue; }
        e -= SZ_IN;
        if (e < SZ_IN)  { pack4(U,   g_Uin, e); continue; }
        e -= SZ_IN;
        if (e < SZ_WQK) { pack4(Wqk, g_Wqk, e); continue; }
        e -= SZ_WQK;
        if (e < SZ_WH)  { pack4(Wv1, g_Wv1, e); continue; }
        e -= SZ_WH;
        if (e < SZ_WH)  { pack4(Wv2, g_Wv2, e); continue; }
        e -= SZ_WH;
        if (e < SZ_WH)  { pack4(Wu1, g_Wu1, e); continue; }
        e -= SZ_WH;
        if (e < SZ_WH)  { pack4(Wu2, g_Wu2, e); continue; }
        e -= SZ_WH;
        pack4(Wp, g_Wpp, e);
    }
}

// ---------------- tensor-core GEMM + bias, PACKED operands ----------------
__global__ __launch_bounds__(256) void mma_gemm_kernel(
    const uint32_t* __restrict__ A, const uint32_t* __restrict__ B,
    const float* __restrict__ bias, void* __restrict__ Cv,
    int M, int N, int K, int mode)
{
    __shared__ uint32_t As[64*40];
    __shared__ uint32_t Bs[32*68];
    const int m0 = blockIdx.y * 64, n0 = blockIdx.x * 64;
    const int tid = threadIdx.x, lane = tid & 31, w = tid >> 5;
    const int g = lane >> 2, t = lane & 3;
    const int mw = w >> 2, nq = w & 3;

    uint32_t aReg[8], bReg[8];
    #pragma unroll
    for (int i = 0; i < 8; i++) {
        int idx = 256*i + tid;
        aReg[i] = A[(size_t)(m0 + (idx >> 5)) * K + (idx & 31)];
        bReg[i] = B[(size_t)(idx >> 6) * N + n0 + (idx & 63)];
    }
    float acc[2][2][4] = {};

    for (int k0 = 0; k0 < K; k0 += 32) {
        #pragma unroll
        for (int i = 0; i < 8; i++) {
            int idx = 256*i + tid;
            As[(idx >> 5)*40 + (idx & 31)] = aReg[i];
            Bs[(idx >> 6)*68 + (idx & 63)] = bReg[i];
        }
        __syncthreads();
        if (k0 + 32 < K) {
            #pragma unroll
            for (int i = 0; i < 8; i++) {
                int idx = 256*i + tid;
                aReg[i] = A[(size_t)(m0 + (idx >> 5)) * K + k0 + 32 + (idx & 31)];
                bReg[i] = B[(size_t)(k0 + 32 + (idx >> 6)) * N + n0 + (idx & 63)];
            }
        }
        #pragma unroll
        for (int ks = 0; ks < 2; ks++) {
            uint32_t ah[2][4], al[2][4];
            #pragma unroll
            for (int mt = 0; mt < 2; mt++) {
                int r = mw*32 + mt*16 + g;
                int d = ks*16 + 2*t;
                uint2 p0 = *(const uint2*)&As[r*40 + d];
                uint2 p1 = *(const uint2*)&As[(r+8)*40 + d];
                uint2 p2 = *(const uint2*)&As[r*40 + d + 8];
                uint2 p3 = *(const uint2*)&As[(r+8)*40 + d + 8];
                ah[mt][0] = PERM_HI(p0.x, p0.y); al[mt][0] = PERM_LO(p0.x, p0.y);
                ah[mt][1] = PERM_HI(p1.x, p1.y); al[mt][1] = PERM_LO(p1.x, p1.y);
                ah[mt][2] = PERM_HI(p2.x, p2.y); al[mt][2] = PERM_LO(p2.x, p2.y);
                ah[mt][3] = PERM_HI(p3.x, p3.y); al[mt][3] = PERM_LO(p3.x, p3.y);
            }
            #pragma unroll
            for (int nt = 0; nt < 2; nt++) {
                int nn = nq*16 + nt*8 + g;
                int kk = ks*16 + 2*t;
                uint32_t q0 = Bs[kk*68 + nn];
                uint32_t q1 = Bs[(kk+1)*68 + nn];
                uint32_t q2 = Bs[(kk+8)*68 + nn];
                uint32_t q3 = Bs[(kk+9)*68 + nn];
                uint32_t bfh[2] = {PERM_HI(q0, q1), PERM_HI(q2, q3)};
                uint32_t bfl[2] = {PERM_LO(q0, q1), PERM_LO(q2, q3)};
                #pragma unroll
                for (int mt = 0; mt < 2; mt++) {
                    mma_bf16(acc[mt][nt], ah[mt], bfh);
                    mma_bf16(acc[mt][nt], ah[mt], bfl);
                    mma_bf16(acc[mt][nt], al[mt], bfh);
                }
            }
        }
        __syncthreads();
    }

    #pragma unroll
    for (int mt = 0; mt < 2; mt++) {
        int row = m0 + mw*32 + mt*16 + g;
        #pragma unroll
        for (int nt = 0; nt < 2; nt++) {
            int col = n0 + nq*16 + nt*8 + 2*t;
            float b0 = bias[col], b1 = bias[col+1];
            float v0 = acc[mt][nt][0] + b0, v1 = acc[mt][nt][1] + b1;
            float v2 = acc[mt][nt][2] + b0, v3 = acc[mt][nt][3] + b1;
            if (mode == 0) {
                float* C = (float*)Cv;
                C[(size_t)row*N + col]       = v0;
                C[(size_t)row*N + col + 1]   = v1;
                C[(size_t)(row+8)*N + col]     = v2;
                C[(size_t)(row+8)*N + col + 1] = v3;
            } else {
                uint32_t* C = (uint32_t*)Cv;
                C[(size_t)row*N + col]       = bf16_split_elem(v0);
                C[(size_t)row*N + col + 1]   = bf16_split_elem(v1);
                C[(size_t)(row+8)*N + col]     = bf16_split_elem(v2);
                C[(size_t)(row+8)*N + col + 1] = bf16_split_elem(v3);
            }
        }
    }
}

// ---------------- fused gated half-projections (V and U via blockIdx.z) ----------------
__global__ __launch_bounds__(256) void mma_gated_kernel(
    const uint32_t* __restrict__ Xv, const uint32_t* __restrict__ Xu,
    const uint32_t* __restrict__ Wv1p, const float* __restrict__ bv1,
    const uint32_t* __restrict__ Wv2p, const float* __restrict__ bv2,
    const uint32_t* __restrict__ Wu1p, const float* __restrict__ bu1,
    const uint32_t* __restrict__ Wu2p, const float* __restrict__ bu2,
    uint32_t* __restrict__ Yvp, float* __restrict__ Yuf)
{
    __shared__ uint32_t As[64*40];
    __shared__ uint32_t Bs[32*36];
    const int which = blockIdx.z;
    const uint32_t* X  = which ? Xu : Xv;
    const int c0   = blockIdx.x * 32;
    const int head = c0 >> 6;
    const int is2  = (c0 >> 5) & 1;
    const uint32_t* W  = which ? (is2 ? Wu2p : Wu1p) : (is2 ? Wv2p : Wv1p);
    const float*    bb = which ? (is2 ? bu2 : bu1)  : (is2 ? bv2 : bv1);
    const int wc0 = head * 32;
    const uint32_t* Ain = X + (is2 ? 128 : 0);
    const int m0 = blockIdx.y * 64;
    const int tid = threadIdx.x, lane = tid & 31, w = tid >> 5;
    const int g = lane >> 2, t = lane & 3;
    const int mw = w >> 2, nq = w & 3;

    uint32_t aReg[8], bReg[4];
    #pragma unroll
    for (int i = 0; i < 8; i++) {
        int idx = 256*i + tid;
        aReg[i] = Ain[(size_t)(m0 + (idx >> 5)) * 256 + (idx & 31)];
    }
    #pragma unroll
    for (int i = 0; i < 4; i++) {
        int idx = 256*i + tid;
        bReg[i] = W[(size_t)(idx >> 5) * HALF_OUT + wc0 + (idx & 31)];
    }
    float acc[2][4] = {};

    for (int k0 = 0; k0 < 128; k0 += 32) {
        #pragma unroll
        for (int i = 0; i < 8; i++) {
            int idx = 256*i + tid;
            As[(idx >> 5)*40 + (idx & 31)] = aReg[i];
        }
        #pragma unroll
        for (int i = 0; i < 4; i++) {
            int idx = 256*i + tid;
            Bs[(idx >> 5)*36 + (idx & 31)] = bReg[i];
        }
        __syncthreads();
        if (k0 + 32 < 128) {
            #pragma unroll
            for (int i = 0; i < 8; i++) {
                int idx = 256*i + tid;
                aReg[i] = Ain[(size_t)(m0 + (idx >> 5)) * 256 + k0 + 32 + (idx & 31)];
            }
            #pragma unroll
            for (int i = 0; i < 4; i++) {
                int idx = 256*i + tid;
                bReg[i] = W[(size_t)(k0 + 32 + (idx >> 5)) * HALF_OUT + wc0 + (idx & 31)];
            }
        }
        #pragma unroll
        for (int ks = 0; ks < 2; ks++) {
            uint32_t ah[2][4], al[2][4];
            #pragma unroll
            for (int mt = 0; mt < 2; mt++) {
                int r = mw*32 + mt*16 + g;
                int d = ks*16 + 2*t;
                uint2 p0 = *(const uint2*)&As[r*40 + d];
                uint2 p1 = *(const uint2*)&As[(r+8)*40 + d];
                uint2 p2 = *(const uint2*)&As[r*40 + d + 8];
                uint2 p3 = *(const uint2*)&As[(r+8)*40 + d + 8];
                ah[mt][0] = PERM_HI(p0.x, p0.y); al[mt][0] = PERM_LO(p0.x, p0.y);
                ah[mt][1] = PERM_HI(p1.x, p1.y); al[mt][1] = PERM_LO(p1.x, p1.y);
                ah[mt][2] = PERM_HI(p2.x, p2.y); al[mt][2] = PERM_LO(p2.x, p2.y);
                ah[mt][3] = PERM_HI(p3.x, p3.y); al[mt][3] = PERM_LO(p3.x, p3.y);
            }
            {
                int nn = nq*8 + g;
                int kk = ks*16 + 2*t;
                uint32_t q0 = Bs[kk*36 + nn];
                uint32_t q1 = Bs[(kk+1)*36 + nn];
                uint32_t q2 = Bs[(kk+8)*36 + nn];
                uint32_t q3 = Bs[(kk+9)*36 + nn];
                uint32_t bfh[2] = {PERM_HI(q0, q1), PERM_HI(q2, q3)};
                uint32_t bfl[2] = {PERM_LO(q0, q1), PERM_LO(q2, q3)};
                #pragma unroll
                for (int mt = 0; mt < 2; mt++) {
                    mma_bf16(acc[mt], ah[mt], bfh);
                    mma_bf16(acc[mt], ah[mt], bfl);
                    mma_bf16(acc[mt], al[mt], bfh);
                }
            }
        }
        __syncthreads();
    }

    #pragma unroll
    for (int mt = 0; mt < 2; mt++) {
        int row = m0 + mw*32 + mt*16 + g;
        int col = nq*8 + 2*t;
        float b0 = bb[wc0 + col], b1 = bb[wc0 + col + 1];
        float v[4] = {acc[mt][0] + b0, acc[mt][1] + b1, acc[mt][2] + b0, acc[mt][3] + b1};
        #pragma unroll
        for (int j = 0; j < 4; j++) v[j] = v[j] / (1.0f + __expf(-v[j]));
        if (!which) {
            Yvp[(size_t)row*DEXP + c0 + col]       = bf16_split_elem(v[0]);
            Yvp[(size_t)row*DEXP + c0 + col + 1]   = bf16_split_elem(v[1]);
            Yvp[(size_t)(row+8)*DEXP + c0 + col]     = bf16_split_elem(v[2]);
            Yvp[(size_t)(row+8)*DEXP + c0 + col + 1] = bf16_split_elem(v[3]);
        } else {
            Yuf[(size_t)row*DEXP + c0 + col]       = v[0];
            Yuf[(size_t)row*DEXP + c0 + col + 1]   = v[1];
            Yuf[(size_t)(row+8)*DEXP + c0 + col]     = v[2];
            Yuf[(size_t)(row+8)*DEXP + c0 + col + 1] = v[3];
        }
    }
}

// ---------------- fused attention: direct-gmem K/V fragments (no staging, no stage barriers) ----------------
// grid (32 row-tiles, NHEAD, BSZ), 512 threads = 16 warps.
__global__ __launch_bounds__(512, 1) void attn_kernel(
    const uint32_t* __restrict__ Qps, const uint32_t* __restrict__ Vps,
    const float* __restrict__ Uc, float* __restrict__ attn_out,
    float* __restrict__ Gout)
{
    extern __shared__ float sm[];
    float*    Sf   = sm;                          // 32*SPITCH
    uint32_t* Su   = (uint32_t*)sm;
    uint32_t* Qb   = (uint32_t*)(sm + 32*SPITCH); // 32*QPITCH
    float*    wm   = (float*)(Qb + 32*QPITCH);    // [32][16]
    float*    rowInv = wm + 32*16;                // [32]
    float*    R    = sm;                          // overlay [8][32][RPITCH]

    const int r0 = blockIdx.x * AROWS;
    const int h  = blockIdx.y, b = blockIdx.z;
    const int tid  = threadIdx.x;
    const int lane = tid & 31;
    const int w    = tid >> 5;
    const int g    = lane >> 2;
    const int t    = lane & 3;
    const float scale = 0.17677669529663687f * 1.4426950408889634f;  // 1/sqrt(32)*log2(e)

    // ---- Q tile to smem (reused by all warps) ----
    #pragma unroll
    for (int i = 0; i < 2; i++) {
        int idx = 512*i + tid;
        int r = idx >> 5, d = idx & 31;
        Qb[r*QPITCH + d] = Qps[((size_t)(r0 + r) * BSZ + b) * DQK + h*DATT + d];
    }
    __syncthreads();

    // ---- Q fragments ----
    uint32_t qa_hi[2][2][4], qa_lo[2][2][4];
    #pragma unroll
    for (int mt = 0; mt < 2; mt++) {
        int r = mt*16 + g;
        #pragma unroll
        for (int ks = 0; ks < 2; ks++) {
            int d = ks*16 + 2*t;
            uint2 p0 = *(const uint2*)&Qb[r*QPITCH + d];
            uint2 p1 = *(const uint2*)&Qb[(r+8)*QPITCH + d];
            uint2 p2 = *(const uint2*)&Qb[r*QPITCH + d + 8];
            uint2 p3 = *(const uint2*)&Qb[(r+8)*QPITCH + d + 8];
            qa_hi[mt][ks][0] = PERM_HI(p0.x, p0.y); qa_lo[mt][ks][0] = PERM_LO(p0.x, p0.y);
            qa_hi[mt][ks][1] = PERM_HI(p1.x, p1.y); qa_lo[mt][ks][1] = PERM_LO(p1.x, p1.y);
            qa_hi[mt][ks][2] = PERM_HI(p2.x, p2.y); qa_lo[mt][ks][2] = PERM_LO(p2.x, p2.y);
            qa_hi[mt][ks][3] = PERM_HI(p3.x, p3.y); qa_lo[mt][ks][3] = PERM_LO(p3.x, p3.y);
        }
    }

    // ---- phase 1: scores with direct-gmem K fragments; warp w owns keys kt*128 + w*8 + g ----
    float mx[2][2] = {{-1e30f,-1e30f},{-1e30f,-1e30f}};
    const uint32_t* kbase = Qps + (size_t)b*DQK + h*DATT;   // + key*(BSZ*DQK)
    #pragma unroll 2
    for (int kt = 0; kt < 8; kt++) {
        int key = kt*128 + w*8 + g;
        const uint32_t* kp = kbase + (size_t)key * (BSZ*DQK);
        uint32_t bh[2][2], bl[2][2];
        #pragma unroll
        for (int ks = 0; ks < 2; ks++) {
            int d = ks*16 + 2*t;
            uint2 p0 = *(const uint2*)&kp[d];
            uint2 p1 = *(const uint2*)&kp[d + 8];
            bh[ks][0] = PERM_HI(p0.x, p0.y); bl[ks][0] = PERM_LO(p0.x, p0.y);
            bh[ks][1] = PERM_HI(p1.x, p1.y); bl[ks][1] = PERM_LO(p1.x, p1.y);
        }
        #pragma unroll
        for (int mt = 0; mt < 2; mt++) {
            float c[4] = {0.f, 0.f, 0.f, 0.f};
            #pragma unroll
            for (int ks = 0; ks < 2; ks++) {
                mma_bf16(c, qa_hi[mt][ks], bh[ks]);
                mma_bf16(c, qa_hi[mt][ks], bl[ks]);
                mma_bf16(c, qa_lo[mt][ks], bh[ks]);
            }
            c[0] *= scale; c[1] *= scale; c[2] *= scale; c[3] *= scale;
            mx[mt][0] = fmaxf(mx[mt][0], fmaxf(c[0], c[1]));
            mx[mt][1] = fmaxf(mx[mt][1], fmaxf(c[2], c[3]));
            int row = mt*16 + g;
            int col = kt*128 + w*8 + 2*t;
            *(float2*)&Sf[row*SPITCH + col]     = make_float2(c[0], c[1]);
            *(float2*)&Sf[(row+8)*SPITCH + col] = make_float2(c[2], c[3]);
        }
    }
    #pragma unroll
    for (int mt = 0; mt < 2; mt++) {
        #pragma unroll
        for (int j = 0; j < 2; j++) {
            mx[mt][j] = fmaxf(mx[mt][j], __shfl_xor_sync(0xffffffffu, mx[mt][j], 1));
            mx[mt][j] = fmaxf(mx[mt][j], __shfl_xor_sync(0xffffffffu, mx[mt][j], 2));
        }
        if (t == 0) {
            wm[(mt*16 + g)*16 + w]     = mx[mt][0];
            wm[(mt*16 + 8 + g)*16 + w] = mx[mt][1];
        }
    }
    __syncthreads();

    // ---- phase 2: softmax (2 rows per warp); packed e in place; normalized attn out (float4) ----
    #pragma unroll
    for (int rr = 0; rr < 2; rr++) {
        int r = w + 16*rr;
        float* row = Sf + r*SPITCH;
        uint32_t* urow = Su + r*SPITCH;
        float m = wm[r*16 + (lane & 15)];
        #pragma unroll
        for (int o = 8; o; o >>= 1) m = fmaxf(m, __shfl_xor_sync(0xffffffffu, m, o));
        float s = 0.f;
        #pragma unroll 4
        for (int i = 0; i < 16; i++) {
            int k = 2*lane + 64*i;
            float2 x = *(const float2*)&row[k];
            float e0 = exp2f(x.x - m), e1 = exp2f(x.y - m);
            s += e0 + e1;
            uint2 pk = make_uint2(bf16_split_elem(e0), bf16_split_elem(e1));
            *(uint2*)&urow[k] = pk;
        }
        #pragma unroll
        for (int o = 16; o; o >>= 1) s += __shfl_xor_sync(0xffffffffu, s, o);
        float inv = 1.0f / s;
        if (lane == 0) rowInv[r] = inv;
        __syncwarp();
        float* gp = attn_out ? attn_out + (((size_t)(b*NHEAD + h) * LL + (r0 + r)) * LL) : nullptr;
        if (gp) {
            #pragma unroll 2
            for (int i = 0; i < 8; i++) {
                int k = 4*lane + 128*i;
                uint4 p = *(const uint4*)&urow[k];
                *(float4*)&gp[k] = make_float4(bf16_unsplit(p.x) * inv, bf16_unsplit(p.y) * inv,
                                               bf16_unsplit(p.z) * inv, bf16_unsplit(p.w) * inv);
            }
        }
    }
    __syncthreads();

    // ---- phase 3: AV with direct-gmem V fragments; warp = (ks=w>>1, nh=w&1) ----
    const int ks = w >> 1;
    const int nh = w & 1;
    float cav[2][4][4] = {};
    const uint32_t* vbase = Vps + (size_t)b*DEXP + h*HDIM;   // + key*(BSZ*DEXP)
    for (int vt = 0; vt < 8; vt++) {
        int k0 = vt*128 + ks*16 + 2*t;
        const uint32_t* v0 = vbase + (size_t)k0       * (BSZ*DEXP);
        const uint32_t* v1 = vbase + (size_t)(k0 + 1) * (BSZ*DEXP);
        const uint32_t* v8 = vbase + (size_t)(k0 + 8) * (BSZ*DEXP);
        const uint32_t* v9 = vbase + (size_t)(k0 + 9) * (BSZ*DEXP);
        // a-frags (rows mt*16+g, +8) from packed-e S
        uint32_t ah[2][4], al[2][4];
        #pragma unroll
        for (int mt = 0; mt < 2; mt++) {
            int r = mt*16 + g;
            int d = vt*128 + ks*16 + 2*t;
            uint2 p0 = *(const uint2*)&Su[r*SPITCH + d];
            uint2 p1 = *(const uint2*)&Su[(r+8)*SPITCH + d];
            uint2 p2 = *(const uint2*)&Su[r*SPITCH + d + 8];
            uint2 p3 = *(const uint2*)&Su[(r+8)*SPITCH + d + 8];
            ah[mt][0] = PERM_HI(p0.x, p0.y); al[mt][0] = PERM_LO(p0.x, p0.y);
            ah[mt][1] = PERM_HI(p1.x, p1.y); al[mt][1] = PERM_LO(p1.x, p1.y);
            ah[mt][2] = PERM_HI(p2.x, p2.y); al[mt][2] = PERM_LO(p2.x, p2.y);
            ah[mt][3] = PERM_HI(p3.x, p3.y); al[mt][3] = PERM_LO(p3.x, p3.y);
        }
        #pragma unroll
        for (int nt = 0; nt < 4; nt++) {
            int nn = nh*32 + nt*8 + g;
            uint32_t q0 = v0[nn];
            uint32_t q1 = v1[nn];
            uint32_t q2 = v8[nn];
            uint32_t q3 = v9[nn];
            uint32_t bfh[2] = {PERM_HI(q0, q1), PERM_HI(q2, q3)};
            uint32_t bfl[2] = {PERM_LO(q0, q1), PERM_LO(q2, q3)};
            #pragma unroll
            for (int mt = 0; mt < 2; mt++) {
                mma_bf16(cav[mt][nt], ah[mt], bfh);
                mma_bf16(cav[mt][nt], ah[mt], bfl);
                mma_bf16(cav[mt][nt], al[mt], bfh);
            }
        }
    }
    __syncthreads();   // all Su reads done before R overlay

    // ---- reduction across 8 ks groups (overlay R on S region) ----
    #pragma unroll
    for (int mt = 0; mt < 2; mt++) {
        int row = mt*16 + g;
        #pragma unroll
        for (int nt = 0; nt < 4; nt++) {
            int col = nh*32 + nt*8 + 2*t;
            *(float2*)&R[(ks*32 + row)*RPITCH + col]     = make_float2(cav[mt][nt][0], cav[mt][nt][1]);
            *(float2*)&R[(ks*32 + row + 8)*RPITCH + col] = make_float2(cav[mt][nt][2], cav[mt][nt][3]);
        }
    }
    __syncthreads();

    // ---- final: sum 8 partials, normalize, U-gate, write ----
    {
        int rr = tid >> 4;
        int c  = 2*(tid & 15);
        float2 s  = make_float2(0.f, 0.f);
        float2 s2 = make_float2(0.f, 0.f);
        #pragma unroll
        for (int kq = 0; kq < 8; kq++) {
            float2 p  = *(const float2*)&R[(kq*32 + rr)*RPITCH + c];
            float2 p2 = *(const float2*)&R[(kq*32 + rr)*RPITCH + c + 32];
            s.x += p.x;  s.y += p.y;
            s2.x += p2.x; s2.y += p2.y;
        }
        float inv = rowInv[rr];
        size_t gb = ((size_t)(r0 + rr) * BSZ + b) * DEXP + h*HDIM;
        float2 u  = *(const float2*)&Uc[gb + c];
        *(float2*)&Gout[gb + c] = make_float2(s.x*inv*u.x, s.y*inv*u.y);
        float2 u2 = *(const float2*)&Uc[gb + c + 32];
        *(float2*)&Gout[gb + c + 32] = make_float2(s2.x*inv*u2.x, s2.y*inv*u2.y);
    }
}

// ---------------- depthwise 5x5 conv, row-tiled, packed output ----------------
__global__ __launch_bounds__(256) void dwconv_kernel(
    const float* __restrict__ X, const float* __restrict__ Wc, uint32_t* __restrict__ Yp)
{
    extern __shared__ float sm[];
    float* xs = sm;              // [12*32][33]
    float* ws = sm + 384*33;     // [32][25]
    const int c0 = blockIdx.x * 32;
    const int r0 = blockIdx.y * 8;
    const int b  = blockIdx.z;
    const int tid = threadIdx.x;

    #pragma unroll
    for (int i = 0; i < 48; i++) {
        int idx = tid + 256*i;
        int lp = idx >> 5, c = idx & 31;
        int gr = r0 - 2 + (lp >> 5);
        int j  = lp & 31;
        float v = 0.f;
        if (gr >= 0 && gr < 32)
            v = X[((size_t)(gr*32 + j) * BSZ + b) * DEXP + c0 + c];
        xs[lp*33 + c] = v;
    }
    for (int idx = tid; idx < 32*25; idx += 256) {
        int c = idx / 25, tt = idx % 25;
        ws[c*25 + tt] = Wc[(size_t)(c0 + c) * 25 + tt];
    }
    __syncthreads();

    const int c = tid & 31, pr = tid >> 5;
    for (int s = 0; s < 32; s++) {
        int pos = pr + 8*s;
        int rl = pos >> 5, j = pos & 31;
        float acc = 0.f;
        #pragma unroll
        for (int di = 0; di < 5; di++) {
            int li = rl + di;
            #pragma unroll
            for (int dj = 0; dj < 5; dj++) {
                int jj = j + dj - 2;
                if (jj < 0 || jj >= 32) continue;
                acc += xs[(li*32 + jj)*33 + c] * ws[c*25 + di*5 + dj];
            }
        }
        Yp[((size_t)((r0 + rl)*32 + j) * BSZ + b) * DEXP + c0 + c] = bf16_split_elem(acc);
    }
}

// ---------------- launch ----------------
extern "C" void kernel_launch(void* const* d_in, const int* in_sizes, int n_in,
                              void* d_out, int out_size)
{
    const float* Q   = (const float*)d_in[0];
    const float* V   = (const float*)d_in[2];
    const float* U   = (const float*)d_in[3];
    const float* Wqk = (const float*)d_in[4];
    const float* bqk = (const float*)d_in[5];
    const float* Wv1 = (const float*)d_in[6];
    const float* bv1 = (const float*)d_in[7];
    const float* Wv2 = (const float*)d_in[8];
    const float* bv2 = (const float*)d_in[9];
    const float* Wu1 = (const float*)d_in[10];
    const float* bu1 = (const float*)d_in[11];
    const float* Wu2 = (const float*)d_in[12];
    const float* bu2 = (const float*)d_in[13];
    const float* Wcv = (const float*)d_in[14];
    const float* Wp  = (const float*)d_in[15];
    const float* bp  = (const float*)d_in[16];

    float* out  = (float*)d_out;
    float* attn = (out_size > MROWS*DQK) ? out + (size_t)MROWS*DQK : nullptr;

    uint32_t *Qps, *Vps, *Yp, *Qin, *Vin, *Uin, *pWqk, *pWv1, *pWv2, *pWu1, *pWu2, *pWp;
    float *Uc, *G;
    cudaGetSymbolAddress((void**)&Qps, g_Qps);
    cudaGetSymbolAddress((void**)&Vps, g_Vps);
    cudaGetSymbolAddress((void**)&Uc,  g_Uc);
    cudaGetSymbolAddress((void**)&G,   g_G);
    cudaGetSymbolAddress((void**)&Yp,  g_Yp);
    cudaGetSymbolAddress((void**)&Qin, g_Qin);
    cudaGetSymbolAddress((void**)&Vin, g_Vin);
    cudaGetSymbolAddress((void**)&Uin, g_Uin);
    cudaGetSymbolAddress((void**)&pWqk, g_Wqk);
    cudaGetSymbolAddress((void**)&pWv1, g_Wv1);
    cudaGetSymbolAddress((void**)&pWv2, g_Wv2);
    cudaGetSymbolAddress((void**)&pWu1, g_Wu1);
    cudaGetSymbolAddress((void**)&pWu2, g_Wu2);
    cudaGetSymbolAddress((void**)&pWp, g_Wpp);

    // S 32*1032 + Q 32*40 + wm 512 + rowInv 32  -> ~139 KB
    const size_t ATTN_SMEM = (size_t)(32*SPITCH + 32*QPITCH + 32*16 + 32) * 4;
    const size_t CONV_SMEM = (size_t)(384*33 + 32*25) * sizeof(float);
    cudaFuncSetAttribute(attn_kernel,   cudaFuncAttributeMaxDynamicSharedMemorySize, (int)ATTN_SMEM);
    cudaFuncSetAttribute(dwconv_kernel, cudaFuncAttributeMaxDynamicSharedMemorySize, (int)CONV_SMEM);

    // 0) one fused pack launch for all inputs + weights
    pack_all_kernel<<<2048, 256>>>(Q, V, U, Wqk, Wv1, Wv2, Wu1, Wu2, Wp);

    // 1) Qp = Q @ Wqk + bqk -> packed u32
    {
        dim3 grid(DQK/64, MROWS/64);
        mma_gemm_kernel<<<grid, 256>>>(Qin, pWqk, bqk, Qps, MROWS, DQK, DQK, 1);
    }
    // 2) Vc packed + Uc fp32 in ONE launch
    {
        dim3 grid(16, MROWS/64, 2);
        mma_gated_kernel<<<grid, 256>>>(Vin, Uin, pWv1, bv1, pWv2, bv2,
                                        pWu1, bu1, pWu2, bu2, Vps, Uc);
    }
    // 3) attention
    {
        dim3 grid(LL/AROWS, NHEAD, BSZ);
        attn_kernel<<<grid, 512, ATTN_SMEM>>>(Qps, Vps, Uc, attn, G);
    }
    // 4) depthwise conv -> packed Y
    {
        dim3 grid(16, 4, BSZ);
        dwconv_kernel<<<grid, 256, CONV_SMEM>>>(G, Wcv, Yp);
    }
    // 5) outputs = Y @ Wp + bp
    {
        dim3 grid(DQK/64, MROWS/64);
        mma_gemm_kernel<<<grid, 256>>>(Yp, pWp, bp, out, MROWS, DQK, DEXP, 0);
    }
}